// round 9
// baseline (speedup 1.0000x reference)
#include <cuda_runtime.h>
#include <cuda_bf16.h>
#include <cstdint>

// Problem constants
constexpr int CDIM  = 384;
constexpr int NHEAD = 12;
constexpr int DHEAD = 32;
constexpr int NB    = 16;
constexpr int NN    = 1024;            // 32*32 tokens
constexpr int MT    = NB * NN;         // 16384 rows
constexpr float QK_SCALE = 0.17677669529663687f; // 32^-0.5
constexpr float LOG2E    = 1.4426950408889634f;

// Scratch (static device globals; no runtime allocation)
__device__ float          g_q [(size_t)NB * NHEAD * NN * DHEAD];  // fp32 Q
__device__ __nv_bfloat16  g_kh[(size_t)NB * NHEAD * NN * DHEAD];
__device__ __nv_bfloat16  g_kl[(size_t)NB * NHEAD * NN * DHEAD];
__device__ __nv_bfloat16  g_vh[(size_t)NB * NHEAD * NN * DHEAD];
__device__ __nv_bfloat16  g_vl[(size_t)NB * NHEAD * NN * DHEAD];
__device__ __nv_bfloat16  g_xh[(size_t)MT * CDIM];   // x transposed [m][k]
__device__ __nv_bfloat16  g_xl[(size_t)MT * CDIM];
__device__ __nv_bfloat16  g_wh[(size_t)3 * CDIM * CDIM];   // qkv_w [o][k]
__device__ __nv_bfloat16  g_wl[(size_t)3 * CDIM * CDIM];
__device__ __nv_bfloat16  g_pwh[(size_t)CDIM * CDIM];      // proj_w [o][k]
__device__ __nv_bfloat16  g_pwl[(size_t)CDIM * CDIM];
__device__ __nv_bfloat16  g_aoh[(size_t)MT * CDIM];  // attention out [m][c]
__device__ __nv_bfloat16  g_aol[(size_t)MT * CDIM];

// ===========================================================================
// Helpers
// ===========================================================================
__device__ __forceinline__ float ex2f(float x) {
    float y; asm("ex2.approx.ftz.f32 %0, %1;" : "=f"(y) : "f"(x)); return y;
}
__device__ __forceinline__ void split1(float a, __nv_bfloat16& h, __nv_bfloat16& l) {
    h = __float2bfloat16(a);
    l = __float2bfloat16(a - __bfloat162float(h));
}
// Split (a,b) into bf16 hi pair and bf16 lo (residual) pair, packed b32.
__device__ __forceinline__ void split2(float a, float b, uint32_t& hi, uint32_t& lo) {
    __nv_bfloat16 ah = __float2bfloat16(a), bh = __float2bfloat16(b);
    float ar = a - __bfloat162float(ah), br = b - __bfloat162float(bh);
    __nv_bfloat162 H = __halves2bfloat162(ah, bh);
    __nv_bfloat162 L = __halves2bfloat162(__float2bfloat16(ar), __float2bfloat16(br));
    hi = *(uint32_t*)&H; lo = *(uint32_t*)&L;
}
__device__ __forceinline__ uint32_t smem_u32(const void* p) {
    uint32_t a;
    asm("{ .reg .u64 t; cvta.to.shared.u64 t, %1; cvt.u32.u64 %0, t; }"
        : "=r"(a) : "l"(p));
    return a;
}
#define LDMX2(r0, r1, addr) \
    asm volatile("ldmatrix.sync.aligned.m8n8.x2.shared.b16 {%0,%1}, [%2];" \
                 : "=r"(r0), "=r"(r1) : "r"(addr))
#define LDMX2T(r0, r1, addr) \
    asm volatile("ldmatrix.sync.aligned.m8n8.x2.trans.shared.b16 {%0,%1}, [%2];" \
                 : "=r"(r0), "=r"(r1) : "r"(addr))
#define LDMX4(r, addr) \
    asm volatile("ldmatrix.sync.aligned.m8n8.x4.shared.b16 {%0,%1,%2,%3}, [%4];" \
                 : "=r"((r)[0]), "=r"((r)[1]), "=r"((r)[2]), "=r"((r)[3]) : "r"(addr))
__device__ __forceinline__ void mma_bf16(float* d, const uint32_t* a,
                                         uint32_t b0, uint32_t b1) {
    asm volatile(
        "mma.sync.aligned.m16n8k16.row.col.f32.bf16.bf16.f32 "
        "{%0,%1,%2,%3}, {%4,%5,%6,%7}, {%8,%9}, {%0,%1,%2,%3};"
        : "+f"(d[0]), "+f"(d[1]), "+f"(d[2]), "+f"(d[3])
        : "r"(a[0]), "r"(a[1]), "r"(a[2]), "r"(a[3]), "r"(b0), "r"(b1));
}
#define CP_ASYNC16(saddr, gptr) \
    asm volatile("cp.async.ca.shared.global [%0], [%1], 16;" \
                 :: "r"(saddr), "l"(gptr) : "memory")
#define CP_COMMIT() asm volatile("cp.async.commit_group;" ::: "memory")
#define CP_WAIT(n)  asm volatile("cp.async.wait_group %0;" :: "n"(n) : "memory")

// ---------------------------------------------------------------------------
// Kernel 0a: transpose+split x [b,c,n] fp32  ->  g_xh/g_xl [m=b*NN+n][k=c] bf16
// ---------------------------------------------------------------------------
__global__ __launch_bounds__(256) void convert_x(const float* __restrict__ x) {
    __shared__ float tile[32][33];
    const int b  = blockIdx.z;
    const int n0 = blockIdx.x * 32;
    const int c0 = blockIdx.y * 32;
    const int tx = threadIdx.x, ty = threadIdx.y;   // (32, 8)
    #pragma unroll
    for (int j = 0; j < 4; j++) {
        int c = c0 + ty + j * 8;
        tile[ty + j * 8][tx] = x[((size_t)b * CDIM + c) * NN + n0 + tx];
    }
    __syncthreads();
    #pragma unroll
    for (int j = 0; j < 4; j++) {
        int n = n0 + ty + j * 8;
        float v = tile[tx][ty + j * 8];
        __nv_bfloat16 h, l; split1(v, h, l);
        size_t idx = ((size_t)b * NN + n) * CDIM + c0 + tx;
        g_xh[idx] = h; g_xl[idx] = l;
    }
}

// ---------------------------------------------------------------------------
// Kernel 0b: split weights (qkv_w and proj_w) into bf16 hi/lo.
// ---------------------------------------------------------------------------
__global__ __launch_bounds__(256) void convert_w(const float* __restrict__ qkv_w,
                                                 const float* __restrict__ proj_w) {
    const int i = blockIdx.x * 256 + threadIdx.x;
    const int NW = 3 * CDIM * CDIM;
    if (i < NW) {
        __nv_bfloat16 h, l; split1(qkv_w[i], h, l);
        g_wh[i] = h; g_wl[i] = l;
    }
    if (i < CDIM * CDIM) {
        __nv_bfloat16 h, l; split1(proj_w[i], h, l);
        g_pwh[i] = h; g_pwl[i] = l;
    }
}

// ---------------------------------------------------------------------------
// Kernel 1: QKV GEMM on mma.sync bf16x3 (unchanged, verified).
// ---------------------------------------------------------------------------
constexpr int GROWB = 80;   // 32 bf16 = 64B data + 16B pad

__global__ __launch_bounds__(256) void qkv_mma() {
    __shared__ __align__(16) char sAh[128 * GROWB], sAl[128 * GROWB];
    __shared__ __align__(16) char sBh[128 * GROWB], sBl[128 * GROWB];

    const int tid  = threadIdx.x;
    const int w    = tid >> 5, lane = tid & 31;
    const int mw   = w & 1,   ow   = w >> 1;      // warp tile: 64m x 32o
    const int m0   = blockIdx.x * 128;
    const int o0   = blockIdx.y * 128;
    const int b    = m0 >> 10;

    const uint32_t ah_s = smem_u32(sAh), al_s = smem_u32(sAl);
    const uint32_t bh_s = smem_u32(sBh), bl_s = smem_u32(sBl);

    float acc[4][4][4];
    #pragma unroll
    for (int mt = 0; mt < 4; mt++)
        #pragma unroll
        for (int nt = 0; nt < 4; nt++)
            #pragma unroll
            for (int e = 0; e < 4; e++) acc[mt][nt][e] = 0.f;

    for (int it = 0; it < CDIM / 32; it++) {
        const int k0 = it * 32;
        __syncthreads();
        #pragma unroll
        for (int r = 0; r < 2; r++) {
            int idx = tid + 256 * r;
            int row = idx >> 2, c4 = idx & 3;
            size_t ga = (size_t)(m0 + row) * CDIM + k0 + c4 * 8;
            size_t gb = (size_t)(o0 + row) * CDIM + k0 + c4 * 8;
            *(uint4*)(sAh + row * GROWB + c4 * 16) = *(const uint4*)(g_xh + ga);
            *(uint4*)(sAl + row * GROWB + c4 * 16) = *(const uint4*)(g_xl + ga);
            *(uint4*)(sBh + row * GROWB + c4 * 16) = *(const uint4*)(g_wh + gb);
            *(uint4*)(sBl + row * GROWB + c4 * 16) = *(const uint4*)(g_wl + gb);
        }
        __syncthreads();

        #pragma unroll
        for (int ks = 0; ks < 2; ks++) {
            uint32_t ah[4][4], al[4][4];
            const uint32_t aoff = (uint32_t)((mw * 64 + (lane & 15)) * GROWB
                                             + (ks * 16 + (lane >> 4) * 8) * 2);
            #pragma unroll
            for (int mt = 0; mt < 4; mt++) {
                LDMX4(ah[mt], ah_s + aoff + mt * 16 * GROWB);
                LDMX4(al[mt], al_s + aoff + mt * 16 * GROWB);
            }
            const uint32_t boff = (uint32_t)((ow * 32 + (lane & 7)) * GROWB
                                             + (ks * 16 + ((lane >> 3) & 1) * 8) * 2);
            #pragma unroll
            for (int nt = 0; nt < 4; nt++) {
                uint32_t b0, b1, c0r, c1;
                LDMX2(b0, b1, bh_s + boff + nt * 8 * GROWB);
                LDMX2(c0r, c1, bl_s + boff + nt * 8 * GROWB);
                #pragma unroll
                for (int mt = 0; mt < 4; mt++) {
                    mma_bf16(acc[mt][nt], ah[mt], b0, b1);
                    mma_bf16(acc[mt][nt], ah[mt], c0r, c1);
                    mma_bf16(acc[mt][nt], al[mt], b0, b1);
                }
            }
        }
    }

    // Epilogue: scatter to Q (fp32) / K,V (bf16 hi+lo), layout [bh][n][d].
    const int g = lane >> 2, t4 = lane & 3;
    #pragma unroll
    for (int mt = 0; mt < 4; mt++) {
        const int n = (m0 + mw * 64 + mt * 16 + g) & (NN - 1);
        #pragma unroll
        for (int nt = 0; nt < 4; nt++) {
            const int o   = o0 + ow * 32 + nt * 8 + t4 * 2;
            const int wch = o / CDIM;
            const int rem = o % CDIM;
            const int h   = rem >> 5, d = rem & 31;
            const size_t base0 = ((size_t)(b * NHEAD + h) * NN + n) * DHEAD + d;
            const size_t base1 = base0 + 8 * DHEAD;   // row n+8
            float* ac = acc[mt][nt];
            if (wch == 0) {
                *(float2*)(g_q + base0) = make_float2(ac[0], ac[1]);
                *(float2*)(g_q + base1) = make_float2(ac[2], ac[3]);
            } else {
                __nv_bfloat16* dh = (wch == 1) ? g_kh : g_vh;
                __nv_bfloat16* dl = (wch == 1) ? g_kl : g_vl;
                uint32_t h0, l0, h1, l1;
                split2(ac[0], ac[1], h0, l0);
                split2(ac[2], ac[3], h1, l1);
                *(uint32_t*)(dh + base0) = h0; *(uint32_t*)(dl + base0) = l0;
                *(uint32_t*)(dh + base1) = h1; *(uint32_t*)(dl + base1) = l1;
            }
        }
    }
}

// ---------------------------------------------------------------------------
// Kernel 2: flash attention, bf16x3 mma.sync, interleaved S/softmax/PV,
// cp.async double buffering.  NOW 8 warps x 16 query rows (256 threads) to
// double occupancy: per-thread register state halves vs the 4-warp version.
// CTA = (b,h) x 128 queries; 16 chunks of 64 keys.
// ---------------------------------------------------------------------------
constexpr int ROWB = 80;

__global__ __launch_bounds__(256, 3) void attn_mma() {
    __shared__ __align__(16) char sk_h[2][64 * ROWB];
    __shared__ __align__(16) char sk_l[2][64 * ROWB];
    __shared__ __align__(16) char sv_h[2][64 * ROWB];
    __shared__ __align__(16) char sv_l[2][64 * ROWB];

    const int tid = threadIdx.x;
    const int w   = tid >> 5;        // 0..7, warp owns query rows [w*16, w*16+16)
    const int l   = tid & 31;
    const int g   = l >> 2;
    const int t4  = l & 3;
    const int lane = l & 15;
    const int bh  = blockIdx.y;
    const int n0  = blockIdx.x * 128;

    const uint32_t skh0 = smem_u32(sk_h[0]), skl0 = smem_u32(sk_l[0]);
    const uint32_t svh0 = smem_u32(sv_h[0]), svl0 = smem_u32(sv_l[0]);
    constexpr uint32_t BUFB = 64 * ROWB;

    // ---- per-thread chunk-load geometry (256 threads cover 64 rows x 4) ----
    const int    ldrow = tid >> 2, ldc4 = tid & 3;
    const size_t ldsrc = ((size_t)bh * NN + ldrow) * DHEAD + ldc4 * 8;
    const uint32_t lddst = (uint32_t)(ldrow * ROWB + ldc4 * 16);

    // ---- prologue: async-load chunk 0 into buffer 0 ----
    CP_ASYNC16(skh0 + lddst, g_kh + ldsrc);
    CP_ASYNC16(skl0 + lddst, g_kl + ldsrc);
    CP_ASYNC16(svh0 + lddst, g_vh + ldsrc);
    CP_ASYNC16(svl0 + lddst, g_vl + ldsrc);
    CP_COMMIT();

    // ---- Q fragments (scale*log2e folded), bf16 hi/lo, one m16 tile ----
    uint32_t qh[2][4], ql[2][4];
    {
        const float qs = QK_SCALE * LOG2E;
        const float* qb = g_q + ((size_t)bh * NN + n0 + w * 16) * DHEAD;
        #pragma unroll
        for (int ks = 0; ks < 2; ks++) {
            int rA = g, rB = g + 8, kk = ks * 16 + t4 * 2;
            float2 v0 = *(const float2*)(qb + rA * DHEAD + kk);
            float2 v1 = *(const float2*)(qb + rB * DHEAD + kk);
            float2 v2 = *(const float2*)(qb + rA * DHEAD + kk + 8);
            float2 v3 = *(const float2*)(qb + rB * DHEAD + kk + 8);
            split2(v0.x * qs, v0.y * qs, qh[ks][0], ql[ks][0]);
            split2(v1.x * qs, v1.y * qs, qh[ks][1], ql[ks][1]);
            split2(v2.x * qs, v2.y * qs, qh[ks][2], ql[ks][2]);
            split2(v3.x * qs, v3.y * qs, qh[ks][3], ql[ks][3]);
        }
    }

    float of[4][4];
    #pragma unroll
    for (int nt = 0; nt < 4; nt++)
        #pragma unroll
        for (int e = 0; e < 4; e++) of[nt][e] = 0.f;

    float lA = 0.f, lB = 0.f;

    for (int it = 0; it < 16; it++) {
        const uint32_t bofs = (uint32_t)(it & 1) * BUFB;
        if (it < 15) {
            const uint32_t nofs = (uint32_t)((it + 1) & 1) * BUFB;
            const size_t koff = (size_t)(it + 1) * 64 * DHEAD;
            CP_ASYNC16(skh0 + nofs + lddst, g_kh + ldsrc + koff);
            CP_ASYNC16(skl0 + nofs + lddst, g_kl + ldsrc + koff);
            CP_ASYNC16(svh0 + nofs + lddst, g_vh + ldsrc + koff);
            CP_ASYNC16(svl0 + nofs + lddst, g_vl + ldsrc + koff);
            CP_COMMIT();
            CP_WAIT(1);          // chunk `it` complete (next may be in flight)
        } else {
            CP_WAIT(0);
        }
        __syncthreads();

        // ---- interleaved: per 16-key group: S-mma -> exp -> split -> PV ----
        #pragma unroll
        for (int s = 0; s < 4; s++) {
            uint32_t pfh[4], pfl[4];   // A-fragments of P for this key group
            #pragma unroll
            for (int hhf = 0; hhf < 2; hhf++) {
                const int nt = 2 * s + hhf;
                float sf[4] = {0.f, 0.f, 0.f, 0.f};
                #pragma unroll
                for (int ks = 0; ks < 2; ks++) {
                    uint32_t aoff = bofs + (uint32_t)((nt * 8 + (lane & 7)) * ROWB
                                               + (ks * 16 + (lane >> 3) * 8) * 2);
                    uint32_t bh0, bh1, bl0, bl1;
                    LDMX2(bh0, bh1, skh0 + aoff);
                    LDMX2(bl0, bl1, skl0 + aoff);
                    mma_bf16(sf, qh[ks], bh0, bh1);
                    mma_bf16(sf, qh[ks], bl0, bl1);
                    mma_bf16(sf, ql[ks], bh0, bh1);
                }
                float p0 = ex2f(sf[0]);
                float p1 = ex2f(sf[1]);
                float p2 = ex2f(sf[2]);
                float p3 = ex2f(sf[3]);
                lA += p0 + p1;
                lB += p2 + p3;
                split2(p0, p1, pfh[hhf * 2],     pfl[hhf * 2]);
                split2(p2, p3, pfh[hhf * 2 + 1], pfl[hhf * 2 + 1]);
            }
            // ---- O += P.V for keys [s*16, s*16+16) ----
            #pragma unroll
            for (int nt = 0; nt < 4; nt++) {
                uint32_t voff = bofs + (uint32_t)((s * 16 + lane) * ROWB + nt * 16);
                uint32_t vh0, vh1, vl0, vl1;
                LDMX2T(vh0, vh1, svh0 + voff);
                LDMX2T(vl0, vl1, svl0 + voff);
                mma_bf16(of[nt], pfh, vh0, vh1);
                mma_bf16(of[nt], pfh, vl0, vl1);
                mma_bf16(of[nt], pfl, vh0, vh1);
            }
        }
        __syncthreads();
    }

    // ---- normalize + write g_aoh/g_aol [m][c] (bf16 hi/lo for proj) ----
    const int bb = bh / NHEAD, hh = bh % NHEAD;
    lA += __shfl_xor_sync(0xffffffffu, lA, 1);
    lA += __shfl_xor_sync(0xffffffffu, lA, 2);
    lB += __shfl_xor_sync(0xffffffffu, lB, 1);
    lB += __shfl_xor_sync(0xffffffffu, lB, 2);
    const float ia = 1.f / lA, ib = 1.f / lB;
    const int rA = n0 + w * 16 + g;
    const size_t baseA = ((size_t)(bb * NN) + rA) * CDIM + hh * DHEAD;
    const size_t baseB = baseA + (size_t)8 * CDIM;
    #pragma unroll
    for (int nt = 0; nt < 4; nt++) {
        int col = nt * 8 + t4 * 2;
        uint32_t h0, l0, h1, l1;
        split2(of[nt][0] * ia, of[nt][1] * ia, h0, l0);
        split2(of[nt][2] * ib, of[nt][3] * ib, h1, l1);
        *(uint32_t*)(g_aoh + baseA + col) = h0;
        *(uint32_t*)(g_aol + baseA + col) = l0;
        *(uint32_t*)(g_aoh + baseB + col) = h1;
        *(uint32_t*)(g_aol + baseB + col) = l1;
    }
}

// ---------------------------------------------------------------------------
// Kernel 3: projection GEMM on mma.sync bf16x3 + bias (unchanged, verified).
// ---------------------------------------------------------------------------
__global__ __launch_bounds__(256) void proj_mma(const float* __restrict__ bias,
                                                float* __restrict__ out) {
    __shared__ __align__(16) char sAh[128 * GROWB], sAl[128 * GROWB];
    __shared__ __align__(16) char sBh[128 * GROWB], sBl[128 * GROWB];

    const int tid  = threadIdx.x;
    const int w    = tid >> 5, lane = tid & 31;
    const int mw   = w & 1,   ow   = w >> 1;
    const int m0   = blockIdx.x * 128;
    const int o0   = blockIdx.y * 128;
    const int b    = m0 >> 10;

    const uint32_t ah_s = smem_u32(sAh), al_s = smem_u32(sAl);
    const uint32_t bh_s = smem_u32(sBh), bl_s = smem_u32(sBl);

    float acc[4][4][4];
    #pragma unroll
    for (int mt = 0; mt < 4; mt++)
        #pragma unroll
        for (int nt = 0; nt < 4; nt++)
            #pragma unroll
            for (int e = 0; e < 4; e++) acc[mt][nt][e] = 0.f;

    for (int it = 0; it < CDIM / 32; it++) {
        const int k0 = it * 32;
        __syncthreads();
        #pragma unroll
        for (int r = 0; r < 2; r++) {
            int idx = tid + 256 * r;
            int row = idx >> 2, c4 = idx & 3;
            size_t ga = (size_t)(m0 + row) * CDIM + k0 + c4 * 8;
            size_t gb = (size_t)(o0 + row) * CDIM + k0 + c4 * 8;
            *(uint4*)(sAh + row * GROWB + c4 * 16) = *(const uint4*)(g_aoh + ga);
            *(uint4*)(sAl + row * GROWB + c4 * 16) = *(const uint4*)(g_aol + ga);
            *(uint4*)(sBh + row * GROWB + c4 * 16) = *(const uint4*)(g_pwh + gb);
            *(uint4*)(sBl + row * GROWB + c4 * 16) = *(const uint4*)(g_pwl + gb);
        }
        __syncthreads();

        #pragma unroll
        for (int ks = 0; ks < 2; ks++) {
            uint32_t ah[4][4], al[4][4];
            const uint32_t aoff = (uint32_t)((mw * 64 + (lane & 15)) * GROWB
                                             + (ks * 16 + (lane >> 4) * 8) * 2);
            #pragma unroll
            for (int mt = 0; mt < 4; mt++) {
                LDMX4(ah[mt], ah_s + aoff + mt * 16 * GROWB);
                LDMX4(al[mt], al_s + aoff + mt * 16 * GROWB);
            }
            const uint32_t boff = (uint32_t)((ow * 32 + (lane & 7)) * GROWB
                                             + (ks * 16 + ((lane >> 3) & 1) * 8) * 2);
            #pragma unroll
            for (int nt = 0; nt < 4; nt++) {
                uint32_t b0, b1, c0r, c1;
                LDMX2(b0, b1, bh_s + boff + nt * 8 * GROWB);
                LDMX2(c0r, c1, bl_s + boff + nt * 8 * GROWB);
                #pragma unroll
                for (int mt = 0; mt < 4; mt++) {
                    mma_bf16(acc[mt][nt], ah[mt], b0, b1);
                    mma_bf16(acc[mt][nt], ah[mt], c0r, c1);
                    mma_bf16(acc[mt][nt], al[mt], b0, b1);
                }
            }
        }
    }

    // Epilogue: out[b][o][n] = acc + bias[o]
    const int g = lane >> 2, t4 = lane & 3;
    #pragma unroll
    for (int nt = 0; nt < 4; nt++) {
        const int o = o0 + ow * 32 + nt * 8 + t4 * 2;
        const float b0v = bias[o], b1v = bias[o + 1];
        float* r0 = out + ((size_t)b * CDIM + o) * NN;
        float* r1 = r0 + NN;
        #pragma unroll
        for (int mt = 0; mt < 4; mt++) {
            const int n = (m0 + mw * 64 + mt * 16 + g) & (NN - 1);
            float* ac = acc[mt][nt];
            r0[n]     = ac[0] + b0v;
            r1[n]     = ac[1] + b1v;
            r0[n + 8] = ac[2] + b0v;
            r1[n + 8] = ac[3] + b1v;
        }
    }
}

// ---------------------------------------------------------------------------
extern "C" void kernel_launch(void* const* d_in, const int* in_sizes, int n_in,
                              void* d_out, int out_size) {
    const float* x      = (const float*)d_in[0];   // [16,384,32,32]
    const float* qkv_w  = (const float*)d_in[1];   // [1152,384]
    const float* proj_w = (const float*)d_in[2];   // [384,384]
    const float* proj_b = (const float*)d_in[3];   // [384]
    float* out = (float*)d_out;                    // [16,384,32,32]

    convert_x<<<dim3(NN / 32, CDIM / 32, NB), dim3(32, 8)>>>(x);
    convert_w<<<(3 * CDIM * CDIM + 255) / 256, 256>>>(qkv_w, proj_w);
    qkv_mma<<<dim3(MT / 128, (3 * CDIM) / 128), 256>>>();
    attn_mma<<<dim3(NN / 128, NB * NHEAD), 256>>>();
    proj_mma<<<dim3(MT / 128, CDIM / 128), 256>>>(proj_b, out);
}

// round 11
// speedup vs baseline: 1.0100x; 1.0100x over previous
#include <cuda_runtime.h>
#include <cuda_bf16.h>
#include <cstdint>

// Problem constants
constexpr int CDIM  = 384;
constexpr int NHEAD = 12;
constexpr int DHEAD = 32;
constexpr int NB    = 16;
constexpr int NN    = 1024;            // 32*32 tokens
constexpr int MT    = NB * NN;         // 16384 rows
constexpr float QK_SCALE = 0.17677669529663687f; // 32^-0.5
constexpr float LOG2E    = 1.4426950408889634f;

// Scratch (static device globals; no runtime allocation)
__device__ float          g_q [(size_t)NB * NHEAD * NN * DHEAD];  // fp32 Q
__device__ __nv_bfloat16  g_kh[(size_t)NB * NHEAD * NN * DHEAD];
__device__ __nv_bfloat16  g_kl[(size_t)NB * NHEAD * NN * DHEAD];
__device__ __nv_bfloat16  g_vh[(size_t)NB * NHEAD * NN * DHEAD];
__device__ __nv_bfloat16  g_vl[(size_t)NB * NHEAD * NN * DHEAD];
__device__ __nv_bfloat16  g_xh[(size_t)MT * CDIM];   // x transposed [m][k]
__device__ __nv_bfloat16  g_xl[(size_t)MT * CDIM];
__device__ __nv_bfloat16  g_wh[(size_t)3 * CDIM * CDIM];   // qkv_w [o][k]
__device__ __nv_bfloat16  g_wl[(size_t)3 * CDIM * CDIM];
__device__ __nv_bfloat16  g_pwh[(size_t)CDIM * CDIM];      // proj_w [o][k]
__device__ __nv_bfloat16  g_pwl[(size_t)CDIM * CDIM];
__device__ __nv_bfloat16  g_aoh[(size_t)MT * CDIM];  // attention out [m][c]
__device__ __nv_bfloat16  g_aol[(size_t)MT * CDIM];

// ===========================================================================
// Helpers
// ===========================================================================
__device__ __forceinline__ float ex2f(float x) {
    float y; asm("ex2.approx.ftz.f32 %0, %1;" : "=f"(y) : "f"(x)); return y;
}
__device__ __forceinline__ void split1(float a, __nv_bfloat16& h, __nv_bfloat16& l) {
    h = __float2bfloat16(a);
    l = __float2bfloat16(a - __bfloat162float(h));
}
// Split (a,b) into bf16 hi pair and bf16 lo (residual) pair, packed b32.
__device__ __forceinline__ void split2(float a, float b, uint32_t& hi, uint32_t& lo) {
    __nv_bfloat16 ah = __float2bfloat16(a), bh = __float2bfloat16(b);
    float ar = a - __bfloat162float(ah), br = b - __bfloat162float(bh);
    __nv_bfloat162 H = __halves2bfloat162(ah, bh);
    __nv_bfloat162 L = __halves2bfloat162(__float2bfloat16(ar), __float2bfloat16(br));
    hi = *(uint32_t*)&H; lo = *(uint32_t*)&L;
}
__device__ __forceinline__ uint32_t smem_u32(const void* p) {
    uint32_t a;
    asm("{ .reg .u64 t; cvta.to.shared.u64 t, %1; cvt.u32.u64 %0, t; }"
        : "=r"(a) : "l"(p));
    return a;
}
#define LDMX2(r0, r1, addr) \
    asm volatile("ldmatrix.sync.aligned.m8n8.x2.shared.b16 {%0,%1}, [%2];" \
                 : "=r"(r0), "=r"(r1) : "r"(addr))
#define LDMX2T(r0, r1, addr) \
    asm volatile("ldmatrix.sync.aligned.m8n8.x2.trans.shared.b16 {%0,%1}, [%2];" \
                 : "=r"(r0), "=r"(r1) : "r"(addr))
#define LDMX4(r, addr) \
    asm volatile("ldmatrix.sync.aligned.m8n8.x4.shared.b16 {%0,%1,%2,%3}, [%4];" \
                 : "=r"((r)[0]), "=r"((r)[1]), "=r"((r)[2]), "=r"((r)[3]) : "r"(addr))
__device__ __forceinline__ void mma_bf16(float* d, const uint32_t* a,
                                         uint32_t b0, uint32_t b1) {
    asm volatile(
        "mma.sync.aligned.m16n8k16.row.col.f32.bf16.bf16.f32 "
        "{%0,%1,%2,%3}, {%4,%5,%6,%7}, {%8,%9}, {%0,%1,%2,%3};"
        : "+f"(d[0]), "+f"(d[1]), "+f"(d[2]), "+f"(d[3])
        : "r"(a[0]), "r"(a[1]), "r"(a[2]), "r"(a[3]), "r"(b0), "r"(b1));
}
#define CP_ASYNC16(saddr, gptr) \
    asm volatile("cp.async.ca.shared.global [%0], [%1], 16;" \
                 :: "r"(saddr), "l"(gptr) : "memory")
#define CP_COMMIT() asm volatile("cp.async.commit_group;" ::: "memory")
#define CP_WAIT(n)  asm volatile("cp.async.wait_group %0;" :: "n"(n) : "memory")

// ---------------------------------------------------------------------------
// Kernel 0a: transpose+split x [b,c,n] fp32  ->  g_xh/g_xl [m=b*NN+n][k=c] bf16
// ---------------------------------------------------------------------------
__global__ __launch_bounds__(256) void convert_x(const float* __restrict__ x) {
    __shared__ float tile[32][33];
    const int b  = blockIdx.z;
    const int n0 = blockIdx.x * 32;
    const int c0 = blockIdx.y * 32;
    const int tx = threadIdx.x, ty = threadIdx.y;   // (32, 8)
    #pragma unroll
    for (int j = 0; j < 4; j++) {
        int c = c0 + ty + j * 8;
        tile[ty + j * 8][tx] = x[((size_t)b * CDIM + c) * NN + n0 + tx];
    }
    __syncthreads();
    #pragma unroll
    for (int j = 0; j < 4; j++) {
        int n = n0 + ty + j * 8;
        float v = tile[tx][ty + j * 8];
        __nv_bfloat16 h, l; split1(v, h, l);
        size_t idx = ((size_t)b * NN + n) * CDIM + c0 + tx;
        g_xh[idx] = h; g_xl[idx] = l;
    }
}

// ---------------------------------------------------------------------------
// Kernel 0b: split weights (qkv_w and proj_w) into bf16 hi/lo.
// ---------------------------------------------------------------------------
__global__ __launch_bounds__(256) void convert_w(const float* __restrict__ qkv_w,
                                                 const float* __restrict__ proj_w) {
    const int i = blockIdx.x * 256 + threadIdx.x;
    const int NW = 3 * CDIM * CDIM;
    if (i < NW) {
        __nv_bfloat16 h, l; split1(qkv_w[i], h, l);
        g_wh[i] = h; g_wl[i] = l;
    }
    if (i < CDIM * CDIM) {
        __nv_bfloat16 h, l; split1(proj_w[i], h, l);
        g_pwh[i] = h; g_pwl[i] = l;
    }
}

// ---------------------------------------------------------------------------
// Shared GEMM geometry for qkv_mma / proj_mma
// ---------------------------------------------------------------------------
constexpr int GROWB = 80;                 // 32 bf16 = 64B data + 16B pad
constexpr int GARR  = 128 * GROWB;        // one 128-row tile array  (10240 B)
constexpr int QSTG  = 4 * GARR;           // one pipeline stage      (40960 B)
// stage layout: [Ah | Al | Bh | Bl]

// ---------------------------------------------------------------------------
// Kernel 1: QKV GEMM on mma.sync bf16x3, cp.async 2-stage pipelined k-loop.
// C[m][o] = sum_k xT[m][k] * w[o][k].  Block 128m x 128o, 8 warps, k-step 32.
// ---------------------------------------------------------------------------
__global__ __launch_bounds__(256) void qkv_mma() {
    extern __shared__ __align__(16) char dsm[];
    const uint32_t sb = smem_u32(dsm);

    const int tid  = threadIdx.x;
    const int w    = tid >> 5, lane = tid & 31;
    const int mw   = w & 1,   ow   = w >> 1;      // warp tile: 64m x 32o
    const int m0   = blockIdx.x * 128;
    const int o0   = blockIdx.y * 128;
    const int b    = m0 >> 10;

    // per-thread load slot: covers 512 (row,c4) pairs per array in 2 passes
    const int ldrow0 = tid >> 2, ldc4 = tid & 3;

    float acc[4][4][4];
    #pragma unroll
    for (int mt = 0; mt < 4; mt++)
        #pragma unroll
        for (int nt = 0; nt < 4; nt++)
            #pragma unroll
            for (int e = 0; e < 4; e++) acc[mt][nt][e] = 0.f;

    // ---- prologue: async-load k-chunk 0 into stage 0 ----
    #pragma unroll
    for (int r = 0; r < 2; r++) {
        int row = ldrow0 + 64 * r;
        size_t ga = (size_t)(m0 + row) * CDIM + ldc4 * 8;
        size_t gb = (size_t)(o0 + row) * CDIM + ldc4 * 8;
        uint32_t d = (uint32_t)(row * GROWB + ldc4 * 16);
        CP_ASYNC16(sb + d,            g_xh + ga);
        CP_ASYNC16(sb + GARR + d,     g_xl + ga);
        CP_ASYNC16(sb + 2 * GARR + d, g_wh + gb);
        CP_ASYNC16(sb + 3 * GARR + d, g_wl + gb);
    }
    CP_COMMIT();

    constexpr int NIT = CDIM / 32;   // 12
    for (int it = 0; it < NIT; it++) {
        if (it + 1 < NIT) {
            const uint32_t nsb = sb + (uint32_t)((it + 1) & 1) * QSTG;
            const int k0 = (it + 1) * 32;
            #pragma unroll
            for (int r = 0; r < 2; r++) {
                int row = ldrow0 + 64 * r;
                size_t ga = (size_t)(m0 + row) * CDIM + k0 + ldc4 * 8;
                size_t gb = (size_t)(o0 + row) * CDIM + k0 + ldc4 * 8;
                uint32_t d = (uint32_t)(row * GROWB + ldc4 * 16);
                CP_ASYNC16(nsb + d,            g_xh + ga);
                CP_ASYNC16(nsb + GARR + d,     g_xl + ga);
                CP_ASYNC16(nsb + 2 * GARR + d, g_wh + gb);
                CP_ASYNC16(nsb + 3 * GARR + d, g_wl + gb);
            }
            CP_COMMIT();
            CP_WAIT(1);
        } else {
            CP_WAIT(0);
        }
        __syncthreads();

        const uint32_t cb  = sb + (uint32_t)(it & 1) * QSTG;
        const uint32_t ah_s = cb, al_s = cb + GARR;
        const uint32_t bh_s = cb + 2 * GARR, bl_s = cb + 3 * GARR;

        #pragma unroll
        for (int ks = 0; ks < 2; ks++) {
            uint32_t ah[4][4], al[4][4];
            const uint32_t aoff = (uint32_t)((mw * 64 + (lane & 15)) * GROWB
                                             + (ks * 16 + (lane >> 4) * 8) * 2);
            #pragma unroll
            for (int mt = 0; mt < 4; mt++) {
                LDMX4(ah[mt], ah_s + aoff + mt * 16 * GROWB);
                LDMX4(al[mt], al_s + aoff + mt * 16 * GROWB);
            }
            const uint32_t boff = (uint32_t)((ow * 32 + (lane & 7)) * GROWB
                                             + (ks * 16 + ((lane >> 3) & 1) * 8) * 2);
            #pragma unroll
            for (int nt = 0; nt < 4; nt++) {
                uint32_t b0, b1, c0r, c1;
                LDMX2(b0, b1, bh_s + boff + nt * 8 * GROWB);
                LDMX2(c0r, c1, bl_s + boff + nt * 8 * GROWB);
                #pragma unroll
                for (int mt = 0; mt < 4; mt++) {
                    mma_bf16(acc[mt][nt], ah[mt], b0, b1);
                    mma_bf16(acc[mt][nt], ah[mt], c0r, c1);
                    mma_bf16(acc[mt][nt], al[mt], b0, b1);
                }
            }
        }
        __syncthreads();
    }

    // Epilogue: scatter to Q (fp32) / K,V (bf16 hi+lo), layout [bh][n][d].
    const int g = lane >> 2, t4 = lane & 3;
    #pragma unroll
    for (int mt = 0; mt < 4; mt++) {
        const int n = (m0 + mw * 64 + mt * 16 + g) & (NN - 1);
        #pragma unroll
        for (int nt = 0; nt < 4; nt++) {
            const int o   = o0 + ow * 32 + nt * 8 + t4 * 2;
            const int wch = o / CDIM;
            const int rem = o % CDIM;
            const int h   = rem >> 5, d = rem & 31;
            const size_t base0 = ((size_t)(b * NHEAD + h) * NN + n) * DHEAD + d;
            const size_t base1 = base0 + 8 * DHEAD;   // row n+8
            float* ac = acc[mt][nt];
            if (wch == 0) {
                *(float2*)(g_q + base0) = make_float2(ac[0], ac[1]);
                *(float2*)(g_q + base1) = make_float2(ac[2], ac[3]);
            } else {
                __nv_bfloat16* dh = (wch == 1) ? g_kh : g_vh;
                __nv_bfloat16* dl = (wch == 1) ? g_kl : g_vl;
                uint32_t h0, l0, h1, l1;
                split2(ac[0], ac[1], h0, l0);
                split2(ac[2], ac[3], h1, l1);
                *(uint32_t*)(dh + base0) = h0; *(uint32_t*)(dl + base0) = l0;
                *(uint32_t*)(dh + base1) = h1; *(uint32_t*)(dl + base1) = l1;
            }
        }
    }
}

// ---------------------------------------------------------------------------
// Kernel 2: flash attention, bf16x3 mma.sync, interleaved S/softmax/PV,
// cp.async double buffering.  4 warps x 32 query rows (best LDSM:mma ratio),
// reg-capped to 128 for 4 CTAs/SM (16 warps).
// CTA = (b,h) x 128 queries; 16 chunks of 64 keys.
// ---------------------------------------------------------------------------
constexpr int ROWB = 80;

__global__ __launch_bounds__(128, 4) void attn_mma() {
    __shared__ __align__(16) char sk_h[2][64 * ROWB];
    __shared__ __align__(16) char sk_l[2][64 * ROWB];
    __shared__ __align__(16) char sv_h[2][64 * ROWB];
    __shared__ __align__(16) char sv_l[2][64 * ROWB];

    const int tid = threadIdx.x;
    const int w   = tid >> 5;
    const int l   = tid & 31;
    const int g   = l >> 2;
    const int t4  = l & 3;
    const int lane = l & 15;
    const int bh  = blockIdx.y;
    const int n0  = blockIdx.x * 128;

    const uint32_t skh0 = smem_u32(sk_h[0]), skl0 = smem_u32(sk_l[0]);
    const uint32_t svh0 = smem_u32(sv_h[0]), svl0 = smem_u32(sv_l[0]);
    constexpr uint32_t BUFB = 64 * ROWB;

    // ---- per-thread chunk-load geometry ----
    const int    ldrow = tid >> 2, ldc4 = tid & 3;
    const size_t ldsrc0 = ((size_t)bh * NN + ldrow) * DHEAD + ldc4 * 8;
    const uint32_t lddst = (uint32_t)(ldrow * ROWB + ldc4 * 16);
    const size_t ldsrc1 = ldsrc0 + (size_t)32 * DHEAD;
    const uint32_t lddst1 = lddst + 32 * ROWB;

    // ---- prologue: async-load chunk 0 into buffer 0 ----
    CP_ASYNC16(skh0 + lddst,  g_kh + ldsrc0);
    CP_ASYNC16(skh0 + lddst1, g_kh + ldsrc1);
    CP_ASYNC16(skl0 + lddst,  g_kl + ldsrc0);
    CP_ASYNC16(skl0 + lddst1, g_kl + ldsrc1);
    CP_ASYNC16(svh0 + lddst,  g_vh + ldsrc0);
    CP_ASYNC16(svh0 + lddst1, g_vh + ldsrc1);
    CP_ASYNC16(svl0 + lddst,  g_vl + ldsrc0);
    CP_ASYNC16(svl0 + lddst1, g_vl + ldsrc1);
    CP_COMMIT();

    // ---- Q fragments (scale*log2e folded), bf16 hi/lo, loaded once ----
    uint32_t qh[2][2][4], ql[2][2][4];
    {
        const float qs = QK_SCALE * LOG2E;
        const float* qb = g_q + ((size_t)bh * NN + n0 + w * 32) * DHEAD;
        #pragma unroll
        for (int mt = 0; mt < 2; mt++)
            #pragma unroll
            for (int ks = 0; ks < 2; ks++) {
                int rA = mt * 16 + g, rB = rA + 8, kk = ks * 16 + t4 * 2;
                float2 v0 = *(const float2*)(qb + rA * DHEAD + kk);
                float2 v1 = *(const float2*)(qb + rB * DHEAD + kk);
                float2 v2 = *(const float2*)(qb + rA * DHEAD + kk + 8);
                float2 v3 = *(const float2*)(qb + rB * DHEAD + kk + 8);
                split2(v0.x * qs, v0.y * qs, qh[mt][ks][0], ql[mt][ks][0]);
                split2(v1.x * qs, v1.y * qs, qh[mt][ks][1], ql[mt][ks][1]);
                split2(v2.x * qs, v2.y * qs, qh[mt][ks][2], ql[mt][ks][2]);
                split2(v3.x * qs, v3.y * qs, qh[mt][ks][3], ql[mt][ks][3]);
            }
    }

    float of[2][4][4];
    #pragma unroll
    for (int mt = 0; mt < 2; mt++)
        #pragma unroll
        for (int nt = 0; nt < 4; nt++)
            #pragma unroll
            for (int e = 0; e < 4; e++) of[mt][nt][e] = 0.f;

    float lA[2] = {0.f, 0.f}, lB[2] = {0.f, 0.f};

    for (int it = 0; it < 16; it++) {
        const uint32_t bofs = (uint32_t)(it & 1) * BUFB;
        if (it < 15) {
            const uint32_t nofs = (uint32_t)((it + 1) & 1) * BUFB;
            const size_t koff = (size_t)(it + 1) * 64 * DHEAD;
            CP_ASYNC16(skh0 + nofs + lddst,  g_kh + ldsrc0 + koff);
            CP_ASYNC16(skh0 + nofs + lddst1, g_kh + ldsrc1 + koff);
            CP_ASYNC16(skl0 + nofs + lddst,  g_kl + ldsrc0 + koff);
            CP_ASYNC16(skl0 + nofs + lddst1, g_kl + ldsrc1 + koff);
            CP_ASYNC16(svh0 + nofs + lddst,  g_vh + ldsrc0 + koff);
            CP_ASYNC16(svh0 + nofs + lddst1, g_vh + ldsrc1 + koff);
            CP_ASYNC16(svl0 + nofs + lddst,  g_vl + ldsrc0 + koff);
            CP_ASYNC16(svl0 + nofs + lddst1, g_vl + ldsrc1 + koff);
            CP_COMMIT();
            CP_WAIT(1);
        } else {
            CP_WAIT(0);
        }
        __syncthreads();

        // ---- interleaved: per 16-key group: S-mma -> exp -> split -> PV ----
        #pragma unroll
        for (int s = 0; s < 4; s++) {
            uint32_t pfh[2][4], pfl[2][4];
            #pragma unroll
            for (int hhf = 0; hhf < 2; hhf++) {
                const int nt = 2 * s + hhf;
                float sf[2][4];
                #pragma unroll
                for (int mt = 0; mt < 2; mt++)
                    #pragma unroll
                    for (int e = 0; e < 4; e++) sf[mt][e] = 0.f;
                #pragma unroll
                for (int ks = 0; ks < 2; ks++) {
                    uint32_t aoff = bofs + (uint32_t)((nt * 8 + (lane & 7)) * ROWB
                                               + (ks * 16 + (lane >> 3) * 8) * 2);
                    uint32_t bh0, bh1, bl0, bl1;
                    LDMX2(bh0, bh1, skh0 + aoff);
                    LDMX2(bl0, bl1, skl0 + aoff);
                    #pragma unroll
                    for (int mt = 0; mt < 2; mt++) {
                        mma_bf16(sf[mt], qh[mt][ks], bh0, bh1);
                        mma_bf16(sf[mt], qh[mt][ks], bl0, bl1);
                        mma_bf16(sf[mt], ql[mt][ks], bh0, bh1);
                    }
                }
                #pragma unroll
                for (int mt = 0; mt < 2; mt++) {
                    float p0 = ex2f(sf[mt][0]);
                    float p1 = ex2f(sf[mt][1]);
                    float p2 = ex2f(sf[mt][2]);
                    float p3 = ex2f(sf[mt][3]);
                    lA[mt] += p0 + p1;
                    lB[mt] += p2 + p3;
                    split2(p0, p1, pfh[mt][hhf * 2],     pfl[mt][hhf * 2]);
                    split2(p2, p3, pfh[mt][hhf * 2 + 1], pfl[mt][hhf * 2 + 1]);
                }
            }
            // ---- O += P.V for keys [s*16, s*16+16) ----
            #pragma unroll
            for (int nt = 0; nt < 4; nt++) {
                uint32_t voff = bofs + (uint32_t)((s * 16 + lane) * ROWB + nt * 16);
                uint32_t vh0, vh1, vl0, vl1;
                LDMX2T(vh0, vh1, svh0 + voff);
                LDMX2T(vl0, vl1, svl0 + voff);
                #pragma unroll
                for (int mt = 0; mt < 2; mt++) {
                    mma_bf16(of[mt][nt], pfh[mt], vh0, vh1);
                    mma_bf16(of[mt][nt], pfh[mt], vl0, vl1);
                    mma_bf16(of[mt][nt], pfl[mt], vh0, vh1);
                }
            }
        }
        __syncthreads();
    }

    // ---- normalize + write g_aoh/g_aol [m][c] (bf16 hi/lo for proj) ----
    const int bb = bh / NHEAD, hh = bh % NHEAD;
    #pragma unroll
    for (int mt = 0; mt < 2; mt++) {
        float a = lA[mt], b2 = lB[mt];
        a  += __shfl_xor_sync(0xffffffffu, a, 1);
        a  += __shfl_xor_sync(0xffffffffu, a, 2);
        b2 += __shfl_xor_sync(0xffffffffu, b2, 1);
        b2 += __shfl_xor_sync(0xffffffffu, b2, 2);
        const float ia = 1.f / a, ib = 1.f / b2;
        const int rA = n0 + w * 32 + mt * 16 + g;
        const size_t baseA = ((size_t)(bb * NN) + rA) * CDIM + hh * DHEAD;
        const size_t baseB = baseA + (size_t)8 * CDIM;
        #pragma unroll
        for (int nt = 0; nt < 4; nt++) {
            int col = nt * 8 + t4 * 2;
            uint32_t h0, l0, h1, l1;
            split2(of[mt][nt][0] * ia, of[mt][nt][1] * ia, h0, l0);
            split2(of[mt][nt][2] * ib, of[mt][nt][3] * ib, h1, l1);
            *(uint32_t*)(g_aoh + baseA + col) = h0;
            *(uint32_t*)(g_aol + baseA + col) = l0;
            *(uint32_t*)(g_aoh + baseB + col) = h1;
            *(uint32_t*)(g_aol + baseB + col) = l1;
        }
    }
}

// ---------------------------------------------------------------------------
// Kernel 3: projection GEMM on mma.sync bf16x3 + bias, cp.async pipelined.
// ---------------------------------------------------------------------------
__global__ __launch_bounds__(256) void proj_mma(const float* __restrict__ bias,
                                                float* __restrict__ out) {
    extern __shared__ __align__(16) char dsm[];
    const uint32_t sb = smem_u32(dsm);

    const int tid  = threadIdx.x;
    const int w    = tid >> 5, lane = tid & 31;
    const int mw   = w & 1,   ow   = w >> 1;
    const int m0   = blockIdx.x * 128;
    const int o0   = blockIdx.y * 128;
    const int b    = m0 >> 10;

    const int ldrow0 = tid >> 2, ldc4 = tid & 3;

    float acc[4][4][4];
    #pragma unroll
    for (int mt = 0; mt < 4; mt++)
        #pragma unroll
        for (int nt = 0; nt < 4; nt++)
            #pragma unroll
            for (int e = 0; e < 4; e++) acc[mt][nt][e] = 0.f;

    #pragma unroll
    for (int r = 0; r < 2; r++) {
        int row = ldrow0 + 64 * r;
        size_t ga = (size_t)(m0 + row) * CDIM + ldc4 * 8;
        size_t gb = (size_t)(o0 + row) * CDIM + ldc4 * 8;
        uint32_t d = (uint32_t)(row * GROWB + ldc4 * 16);
        CP_ASYNC16(sb + d,            g_aoh + ga);
        CP_ASYNC16(sb + GARR + d,     g_aol + ga);
        CP_ASYNC16(sb + 2 * GARR + d, g_pwh + gb);
        CP_ASYNC16(sb + 3 * GARR + d, g_pwl + gb);
    }
    CP_COMMIT();

    constexpr int NIT = CDIM / 32;
    for (int it = 0; it < NIT; it++) {
        if (it + 1 < NIT) {
            const uint32_t nsb = sb + (uint32_t)((it + 1) & 1) * QSTG;
            const int k0 = (it + 1) * 32;
            #pragma unroll
            for (int r = 0; r < 2; r++) {
                int row = ldrow0 + 64 * r;
                size_t ga = (size_t)(m0 + row) * CDIM + k0 + ldc4 * 8;
                size_t gb = (size_t)(o0 + row) * CDIM + k0 + ldc4 * 8;
                uint32_t d = (uint32_t)(row * GROWB + ldc4 * 16);
                CP_ASYNC16(nsb + d,            g_aoh + ga);
                CP_ASYNC16(nsb + GARR + d,     g_aol + ga);
                CP_ASYNC16(nsb + 2 * GARR + d, g_pwh + gb);
                CP_ASYNC16(nsb + 3 * GARR + d, g_pwl + gb);
            }
            CP_COMMIT();
            CP_WAIT(1);
        } else {
            CP_WAIT(0);
        }
        __syncthreads();

        const uint32_t cb  = sb + (uint32_t)(it & 1) * QSTG;
        const uint32_t ah_s = cb, al_s = cb + GARR;
        const uint32_t bh_s = cb + 2 * GARR, bl_s = cb + 3 * GARR;

        #pragma unroll
        for (int ks = 0; ks < 2; ks++) {
            uint32_t ah[4][4], al[4][4];
            const uint32_t aoff = (uint32_t)((mw * 64 + (lane & 15)) * GROWB
                                             + (ks * 16 + (lane >> 4) * 8) * 2);
            #pragma unroll
            for (int mt = 0; mt < 4; mt++) {
                LDMX4(ah[mt], ah_s + aoff + mt * 16 * GROWB);
                LDMX4(al[mt], al_s + aoff + mt * 16 * GROWB);
            }
            const uint32_t boff = (uint32_t)((ow * 32 + (lane & 7)) * GROWB
                                             + (ks * 16 + ((lane >> 3) & 1) * 8) * 2);
            #pragma unroll
            for (int nt = 0; nt < 4; nt++) {
                uint32_t b0, b1, c0r, c1;
                LDMX2(b0, b1, bh_s + boff + nt * 8 * GROWB);
                LDMX2(c0r, c1, bl_s + boff + nt * 8 * GROWB);
                #pragma unroll
                for (int mt = 0; mt < 4; mt++) {
                    mma_bf16(acc[mt][nt], ah[mt], b0, b1);
                    mma_bf16(acc[mt][nt], ah[mt], c0r, c1);
                    mma_bf16(acc[mt][nt], al[mt], b0, b1);
                }
            }
        }
        __syncthreads();
    }

    // Epilogue: out[b][o][n] = acc + bias[o]
    const int g = lane >> 2, t4 = lane & 3;
    #pragma unroll
    for (int nt = 0; nt < 4; nt++) {
        const int o = o0 + ow * 32 + nt * 8 + t4 * 2;
        const float b0v = bias[o], b1v = bias[o + 1];
        float* r0 = out + ((size_t)b * CDIM + o) * NN;
        float* r1 = r0 + NN;
        #pragma unroll
        for (int mt = 0; mt < 4; mt++) {
            const int n = (m0 + mw * 64 + mt * 16 + g) & (NN - 1);
            float* ac = acc[mt][nt];
            r0[n]     = ac[0] + b0v;
            r1[n]     = ac[1] + b1v;
            r0[n + 8] = ac[2] + b0v;
            r1[n + 8] = ac[3] + b1v;
        }
    }
}

// ---------------------------------------------------------------------------
extern "C" void kernel_launch(void* const* d_in, const int* in_sizes, int n_in,
                              void* d_out, int out_size) {
    const float* x      = (const float*)d_in[0];   // [16,384,32,32]
    const float* qkv_w  = (const float*)d_in[1];   // [1152,384]
    const float* proj_w = (const float*)d_in[2];   // [384,384]
    const float* proj_b = (const float*)d_in[3];   // [384]
    float* out = (float*)d_out;                    // [16,384,32,32]

    cudaFuncSetAttribute(qkv_mma,  cudaFuncAttributeMaxDynamicSharedMemorySize, 2 * QSTG);
    cudaFuncSetAttribute(proj_mma, cudaFuncAttributeMaxDynamicSharedMemorySize, 2 * QSTG);

    convert_x<<<dim3(NN / 32, CDIM / 32, NB), dim3(32, 8)>>>(x);
    convert_w<<<(3 * CDIM * CDIM + 255) / 256, 256>>>(qkv_w, proj_w);
    qkv_mma<<<dim3(MT / 128, (3 * CDIM) / 128), 256, 2 * QSTG>>>();
    attn_mma<<<dim3(NN / 128, NB * NHEAD), 128>>>();
    proj_mma<<<dim3(MT / 128, CDIM / 128), 256, 2 * QSTG>>>(proj_b, out);
}

// round 12
// speedup vs baseline: 1.2421x; 1.2297x over previous
#include <cuda_runtime.h>
#include <cuda_bf16.h>
#include <cuda_fp16.h>
#include <cstdint>

// Problem constants
constexpr int CDIM  = 384;
constexpr int NHEAD = 12;
constexpr int DHEAD = 32;
constexpr int NB    = 16;
constexpr int NN    = 1024;            // 32*32 tokens
constexpr int MT    = NB * NN;         // 16384 rows
constexpr float QK_SCALE = 0.17677669529663687f; // 32^-0.5
constexpr float LOG2E    = 1.4426950408889634f;
constexpr float QS2      = QK_SCALE * LOG2E;     // folded into K at qkv epilogue

// Scratch (static device globals; no runtime allocation)
__device__ float          g_q [(size_t)NB * NHEAD * NN * DHEAD];  // fp32 Q
__device__ __half         g_k [(size_t)NB * NHEAD * NN * DHEAD];  // fp16 K (pre-scaled)
__device__ __half         g_vh[(size_t)NB * NHEAD * NN * DHEAD];  // fp16 V hi
__device__ __half         g_vl[(size_t)NB * NHEAD * NN * DHEAD];  // fp16 V lo
__device__ __nv_bfloat16  g_xh[(size_t)MT * CDIM];   // x transposed [m][k]
__device__ __nv_bfloat16  g_xl[(size_t)MT * CDIM];
__device__ __nv_bfloat16  g_wh[(size_t)3 * CDIM * CDIM];   // qkv_w [o][k]
__device__ __nv_bfloat16  g_wl[(size_t)3 * CDIM * CDIM];
__device__ __nv_bfloat16  g_pwh[(size_t)CDIM * CDIM];      // proj_w [o][k]
__device__ __nv_bfloat16  g_pwl[(size_t)CDIM * CDIM];
__device__ __nv_bfloat16  g_aoh[(size_t)MT * CDIM];  // attention out [m][c]
__device__ __nv_bfloat16  g_aol[(size_t)MT * CDIM];

// ===========================================================================
// Helpers
// ===========================================================================
__device__ __forceinline__ float ex2f(float x) {
    float y; asm("ex2.approx.ftz.f32 %0, %1;" : "=f"(y) : "f"(x)); return y;
}
__device__ __forceinline__ void split1(float a, __nv_bfloat16& h, __nv_bfloat16& l) {
    h = __float2bfloat16(a);
    l = __float2bfloat16(a - __bfloat162float(h));
}
// bf16 pair split (GEMM path, unchanged)
__device__ __forceinline__ void split2(float a, float b, uint32_t& hi, uint32_t& lo) {
    __nv_bfloat16 ah = __float2bfloat16(a), bh = __float2bfloat16(b);
    float ar = a - __bfloat162float(ah), br = b - __bfloat162float(bh);
    __nv_bfloat162 H = __halves2bfloat162(ah, bh);
    __nv_bfloat162 L = __halves2bfloat162(__float2bfloat16(ar), __float2bfloat16(br));
    hi = *(uint32_t*)&H; lo = *(uint32_t*)&L;
}
// fp16 pair split (attention path)
__device__ __forceinline__ void split2h(float a, float b, uint32_t& hi, uint32_t& lo) {
    __half ah = __float2half_rn(a), bh = __float2half_rn(b);
    float ar = a - __half2float(ah), br = b - __half2float(bh);
    __half2 H = __halves2half2(ah, bh);
    __half2 L = __halves2half2(__float2half_rn(ar), __float2half_rn(br));
    hi = *(uint32_t*)&H; lo = *(uint32_t*)&L;
}
__device__ __forceinline__ uint32_t pack_h2(float a, float b) {
    __half2 h = __floats2half2_rn(a, b);
    return *(uint32_t*)&h;
}
__device__ __forceinline__ uint32_t smem_u32(const void* p) {
    uint32_t a;
    asm("{ .reg .u64 t; cvta.to.shared.u64 t, %1; cvt.u32.u64 %0, t; }"
        : "=r"(a) : "l"(p));
    return a;
}
#define LDMX2(r0, r1, addr) \
    asm volatile("ldmatrix.sync.aligned.m8n8.x2.shared.b16 {%0,%1}, [%2];" \
                 : "=r"(r0), "=r"(r1) : "r"(addr))
#define LDMX2T(r0, r1, addr) \
    asm volatile("ldmatrix.sync.aligned.m8n8.x2.trans.shared.b16 {%0,%1}, [%2];" \
                 : "=r"(r0), "=r"(r1) : "r"(addr))
#define LDMX4(r, addr) \
    asm volatile("ldmatrix.sync.aligned.m8n8.x4.shared.b16 {%0,%1,%2,%3}, [%4];" \
                 : "=r"((r)[0]), "=r"((r)[1]), "=r"((r)[2]), "=r"((r)[3]) : "r"(addr))
__device__ __forceinline__ void mma_bf16(float* d, const uint32_t* a,
                                         uint32_t b0, uint32_t b1) {
    asm volatile(
        "mma.sync.aligned.m16n8k16.row.col.f32.bf16.bf16.f32 "
        "{%0,%1,%2,%3}, {%4,%5,%6,%7}, {%8,%9}, {%0,%1,%2,%3};"
        : "+f"(d[0]), "+f"(d[1]), "+f"(d[2]), "+f"(d[3])
        : "r"(a[0]), "r"(a[1]), "r"(a[2]), "r"(a[3]), "r"(b0), "r"(b1));
}
__device__ __forceinline__ void mma_f16(float* d, const uint32_t* a,
                                        uint32_t b0, uint32_t b1) {
    asm volatile(
        "mma.sync.aligned.m16n8k16.row.col.f32.f16.f16.f32 "
        "{%0,%1,%2,%3}, {%4,%5,%6,%7}, {%8,%9}, {%0,%1,%2,%3};"
        : "+f"(d[0]), "+f"(d[1]), "+f"(d[2]), "+f"(d[3])
        : "r"(a[0]), "r"(a[1]), "r"(a[2]), "r"(a[3]), "r"(b0), "r"(b1));
}
#define CP_ASYNC16(saddr, gptr) \
    asm volatile("cp.async.ca.shared.global [%0], [%1], 16;" \
                 :: "r"(saddr), "l"(gptr) : "memory")
#define CP_COMMIT() asm volatile("cp.async.commit_group;" ::: "memory")
#define CP_WAIT(n)  asm volatile("cp.async.wait_group %0;" :: "n"(n) : "memory")

// ---------------------------------------------------------------------------
// Kernel 0a: transpose+split x [b,c,n] fp32  ->  g_xh/g_xl [m=b*NN+n][k=c] bf16
// ---------------------------------------------------------------------------
__global__ __launch_bounds__(256) void convert_x(const float* __restrict__ x) {
    __shared__ float tile[32][33];
    const int b  = blockIdx.z;
    const int n0 = blockIdx.x * 32;
    const int c0 = blockIdx.y * 32;
    const int tx = threadIdx.x, ty = threadIdx.y;   // (32, 8)
    #pragma unroll
    for (int j = 0; j < 4; j++) {
        int c = c0 + ty + j * 8;
        tile[ty + j * 8][tx] = x[((size_t)b * CDIM + c) * NN + n0 + tx];
    }
    __syncthreads();
    #pragma unroll
    for (int j = 0; j < 4; j++) {
        int n = n0 + ty + j * 8;
        float v = tile[tx][ty + j * 8];
        __nv_bfloat16 h, l; split1(v, h, l);
        size_t idx = ((size_t)b * NN + n) * CDIM + c0 + tx;
        g_xh[idx] = h; g_xl[idx] = l;
    }
}

// ---------------------------------------------------------------------------
// Kernel 0b: split weights (qkv_w and proj_w) into bf16 hi/lo.
// ---------------------------------------------------------------------------
__global__ __launch_bounds__(256) void convert_w(const float* __restrict__ qkv_w,
                                                 const float* __restrict__ proj_w) {
    const int i = blockIdx.x * 256 + threadIdx.x;
    const int NW = 3 * CDIM * CDIM;
    if (i < NW) {
        __nv_bfloat16 h, l; split1(qkv_w[i], h, l);
        g_wh[i] = h; g_wl[i] = l;
    }
    if (i < CDIM * CDIM) {
        __nv_bfloat16 h, l; split1(proj_w[i], h, l);
        g_pwh[i] = h; g_pwl[i] = l;
    }
}

// ---------------------------------------------------------------------------
// Kernel 1: QKV GEMM on mma.sync bf16x3 (R8 static-smem version, verified).
// Epilogue now writes K as single fp16 (pre-scaled by QS2) and V as fp16 hi/lo.
// ---------------------------------------------------------------------------
constexpr int GROWB = 80;   // 32 elems * 2B = 64B data + 16B pad

__global__ __launch_bounds__(256) void qkv_mma() {
    __shared__ __align__(16) char sAh[128 * GROWB], sAl[128 * GROWB];
    __shared__ __align__(16) char sBh[128 * GROWB], sBl[128 * GROWB];

    const int tid  = threadIdx.x;
    const int w    = tid >> 5, lane = tid & 31;
    const int mw   = w & 1,   ow   = w >> 1;      // warp tile: 64m x 32o
    const int m0   = blockIdx.x * 128;
    const int o0   = blockIdx.y * 128;
    const int b    = m0 >> 10;

    const uint32_t ah_s = smem_u32(sAh), al_s = smem_u32(sAl);
    const uint32_t bh_s = smem_u32(sBh), bl_s = smem_u32(sBl);

    float acc[4][4][4];
    #pragma unroll
    for (int mt = 0; mt < 4; mt++)
        #pragma unroll
        for (int nt = 0; nt < 4; nt++)
            #pragma unroll
            for (int e = 0; e < 4; e++) acc[mt][nt][e] = 0.f;

    for (int it = 0; it < CDIM / 32; it++) {
        const int k0 = it * 32;
        __syncthreads();
        #pragma unroll
        for (int r = 0; r < 2; r++) {
            int idx = tid + 256 * r;
            int row = idx >> 2, c4 = idx & 3;
            size_t ga = (size_t)(m0 + row) * CDIM + k0 + c4 * 8;
            size_t gb = (size_t)(o0 + row) * CDIM + k0 + c4 * 8;
            *(uint4*)(sAh + row * GROWB + c4 * 16) = *(const uint4*)(g_xh + ga);
            *(uint4*)(sAl + row * GROWB + c4 * 16) = *(const uint4*)(g_xl + ga);
            *(uint4*)(sBh + row * GROWB + c4 * 16) = *(const uint4*)(g_wh + gb);
            *(uint4*)(sBl + row * GROWB + c4 * 16) = *(const uint4*)(g_wl + gb);
        }
        __syncthreads();

        #pragma unroll
        for (int ks = 0; ks < 2; ks++) {
            uint32_t ah[4][4], al[4][4];
            const uint32_t aoff = (uint32_t)((mw * 64 + (lane & 15)) * GROWB
                                             + (ks * 16 + (lane >> 4) * 8) * 2);
            #pragma unroll
            for (int mt = 0; mt < 4; mt++) {
                LDMX4(ah[mt], ah_s + aoff + mt * 16 * GROWB);
                LDMX4(al[mt], al_s + aoff + mt * 16 * GROWB);
            }
            const uint32_t boff = (uint32_t)((ow * 32 + (lane & 7)) * GROWB
                                             + (ks * 16 + ((lane >> 3) & 1) * 8) * 2);
            #pragma unroll
            for (int nt = 0; nt < 4; nt++) {
                uint32_t b0, b1, c0r, c1;
                LDMX2(b0, b1, bh_s + boff + nt * 8 * GROWB);
                LDMX2(c0r, c1, bl_s + boff + nt * 8 * GROWB);
                #pragma unroll
                for (int mt = 0; mt < 4; mt++) {
                    mma_bf16(acc[mt][nt], ah[mt], b0, b1);
                    mma_bf16(acc[mt][nt], ah[mt], c0r, c1);
                    mma_bf16(acc[mt][nt], al[mt], b0, b1);
                }
            }
        }
    }

    // Epilogue: Q -> fp32; K -> fp16 single (scaled by QS2); V -> fp16 hi/lo.
    const int g = lane >> 2, t4 = lane & 3;
    #pragma unroll
    for (int mt = 0; mt < 4; mt++) {
        const int n = (m0 + mw * 64 + mt * 16 + g) & (NN - 1);
        #pragma unroll
        for (int nt = 0; nt < 4; nt++) {
            const int o   = o0 + ow * 32 + nt * 8 + t4 * 2;
            const int wch = o / CDIM;
            const int rem = o % CDIM;
            const int h   = rem >> 5, d = rem & 31;
            const size_t base0 = ((size_t)(b * NHEAD + h) * NN + n) * DHEAD + d;
            const size_t base1 = base0 + 8 * DHEAD;   // row n+8
            float* ac = acc[mt][nt];
            if (wch == 0) {
                *(float2*)(g_q + base0) = make_float2(ac[0], ac[1]);
                *(float2*)(g_q + base1) = make_float2(ac[2], ac[3]);
            } else if (wch == 1) {
                *(uint32_t*)(g_k + base0) = pack_h2(ac[0] * QS2, ac[1] * QS2);
                *(uint32_t*)(g_k + base1) = pack_h2(ac[2] * QS2, ac[3] * QS2);
            } else {
                uint32_t h0, l0, h1, l1;
                split2h(ac[0], ac[1], h0, l0);
                split2h(ac[2], ac[3], h1, l1);
                *(uint32_t*)(g_vh + base0) = h0; *(uint32_t*)(g_vl + base0) = l0;
                *(uint32_t*)(g_vh + base1) = h1; *(uint32_t*)(g_vl + base1) = l1;
            }
        }
    }
}

// ---------------------------------------------------------------------------
// Kernel 2: flash attention, fp16 mma.sync.
//   S = (qh+ql) . k_fp16          (2 terms; K pre-scaled by QS2)
//   P = fp16(exp2(S)) single
//   O += P . (vh+vl)              (2 terms)
// 4 warps x 32 query rows; cp.async double buffering; 16 chunks of 64 keys.
// ---------------------------------------------------------------------------
constexpr int ROWB = 80;

__global__ __launch_bounds__(128, 4) void attn_mma() {
    __shared__ __align__(16) char sk  [2][64 * ROWB];
    __shared__ __align__(16) char sv_h[2][64 * ROWB];
    __shared__ __align__(16) char sv_l[2][64 * ROWB];

    const int tid = threadIdx.x;
    const int w   = tid >> 5;
    const int l   = tid & 31;
    const int g   = l >> 2;
    const int t4  = l & 3;
    const int lane = l & 15;
    const int bh  = blockIdx.y;
    const int n0  = blockIdx.x * 128;

    const uint32_t sk0  = smem_u32(sk[0]);
    const uint32_t svh0 = smem_u32(sv_h[0]), svl0 = smem_u32(sv_l[0]);
    constexpr uint32_t BUFB = 64 * ROWB;

    // ---- per-thread chunk-load geometry ----
    const int    ldrow = tid >> 2, ldc4 = tid & 3;
    const size_t ldsrc0 = ((size_t)bh * NN + ldrow) * DHEAD + ldc4 * 8;
    const uint32_t lddst = (uint32_t)(ldrow * ROWB + ldc4 * 16);
    const size_t ldsrc1 = ldsrc0 + (size_t)32 * DHEAD;
    const uint32_t lddst1 = lddst + 32 * ROWB;

    // ---- prologue: async-load chunk 0 into buffer 0 ----
    CP_ASYNC16(sk0  + lddst,  g_k  + ldsrc0);
    CP_ASYNC16(sk0  + lddst1, g_k  + ldsrc1);
    CP_ASYNC16(svh0 + lddst,  g_vh + ldsrc0);
    CP_ASYNC16(svh0 + lddst1, g_vh + ldsrc1);
    CP_ASYNC16(svl0 + lddst,  g_vl + ldsrc0);
    CP_ASYNC16(svl0 + lddst1, g_vl + ldsrc1);
    CP_COMMIT();

    // ---- Q fragments: fp16 hi/lo split, NO scale (folded into K) ----
    uint32_t qh[2][2][4], ql[2][2][4];
    {
        const float* qb = g_q + ((size_t)bh * NN + n0 + w * 32) * DHEAD;
        #pragma unroll
        for (int mt = 0; mt < 2; mt++)
            #pragma unroll
            for (int ks = 0; ks < 2; ks++) {
                int rA = mt * 16 + g, rB = rA + 8, kk = ks * 16 + t4 * 2;
                float2 v0 = *(const float2*)(qb + rA * DHEAD + kk);
                float2 v1 = *(const float2*)(qb + rB * DHEAD + kk);
                float2 v2 = *(const float2*)(qb + rA * DHEAD + kk + 8);
                float2 v3 = *(const float2*)(qb + rB * DHEAD + kk + 8);
                split2h(v0.x, v0.y, qh[mt][ks][0], ql[mt][ks][0]);
                split2h(v1.x, v1.y, qh[mt][ks][1], ql[mt][ks][1]);
                split2h(v2.x, v2.y, qh[mt][ks][2], ql[mt][ks][2]);
                split2h(v3.x, v3.y, qh[mt][ks][3], ql[mt][ks][3]);
            }
    }

    float of[2][4][4];
    #pragma unroll
    for (int mt = 0; mt < 2; mt++)
        #pragma unroll
        for (int nt = 0; nt < 4; nt++)
            #pragma unroll
            for (int e = 0; e < 4; e++) of[mt][nt][e] = 0.f;

    float lA[2] = {0.f, 0.f}, lB[2] = {0.f, 0.f};

    for (int it = 0; it < 16; it++) {
        const uint32_t bofs = (uint32_t)(it & 1) * BUFB;
        if (it < 15) {
            const uint32_t nofs = (uint32_t)((it + 1) & 1) * BUFB;
            const size_t koff = (size_t)(it + 1) * 64 * DHEAD;
            CP_ASYNC16(sk0  + nofs + lddst,  g_k  + ldsrc0 + koff);
            CP_ASYNC16(sk0  + nofs + lddst1, g_k  + ldsrc1 + koff);
            CP_ASYNC16(svh0 + nofs + lddst,  g_vh + ldsrc0 + koff);
            CP_ASYNC16(svh0 + nofs + lddst1, g_vh + ldsrc1 + koff);
            CP_ASYNC16(svl0 + nofs + lddst,  g_vl + ldsrc0 + koff);
            CP_ASYNC16(svl0 + nofs + lddst1, g_vl + ldsrc1 + koff);
            CP_COMMIT();
            CP_WAIT(1);
        } else {
            CP_WAIT(0);
        }
        __syncthreads();

        // ---- interleaved: per 16-key group: S-mma -> exp -> pack -> PV ----
        #pragma unroll
        for (int s = 0; s < 4; s++) {
            uint32_t pfh[2][4];   // fp16 A-fragments of P for this key group
            #pragma unroll
            for (int hhf = 0; hhf < 2; hhf++) {
                const int nt = 2 * s + hhf;
                float sf[2][4];
                #pragma unroll
                for (int mt = 0; mt < 2; mt++)
                    #pragma unroll
                    for (int e = 0; e < 4; e++) sf[mt][e] = 0.f;
                #pragma unroll
                for (int ks = 0; ks < 2; ks++) {
                    uint32_t aoff = bofs + (uint32_t)((nt * 8 + (lane & 7)) * ROWB
                                               + (ks * 16 + (lane >> 3) * 8) * 2);
                    uint32_t k0f, k1f;
                    LDMX2(k0f, k1f, sk0 + aoff);
                    #pragma unroll
                    for (int mt = 0; mt < 2; mt++) {
                        mma_f16(sf[mt], qh[mt][ks], k0f, k1f);
                        mma_f16(sf[mt], ql[mt][ks], k0f, k1f);
                    }
                }
                #pragma unroll
                for (int mt = 0; mt < 2; mt++) {
                    float p0 = ex2f(sf[mt][0]);
                    float p1 = ex2f(sf[mt][1]);
                    float p2 = ex2f(sf[mt][2]);
                    float p3 = ex2f(sf[mt][3]);
                    lA[mt] += p0 + p1;
                    lB[mt] += p2 + p3;
                    pfh[mt][hhf * 2]     = pack_h2(p0, p1);
                    pfh[mt][hhf * 2 + 1] = pack_h2(p2, p3);
                }
            }
            // ---- O += P.(vh+vl) for keys [s*16, s*16+16) ----
            #pragma unroll
            for (int nt = 0; nt < 4; nt++) {
                uint32_t voff = bofs + (uint32_t)((s * 16 + lane) * ROWB + nt * 16);
                uint32_t vh0, vh1, vl0, vl1;
                LDMX2T(vh0, vh1, svh0 + voff);
                LDMX2T(vl0, vl1, svl0 + voff);
                #pragma unroll
                for (int mt = 0; mt < 2; mt++) {
                    mma_f16(of[mt][nt], pfh[mt], vh0, vh1);
                    mma_f16(of[mt][nt], pfh[mt], vl0, vl1);
                }
            }
        }
        __syncthreads();
    }

    // ---- normalize + write g_aoh/g_aol [m][c] (bf16 hi/lo for proj) ----
    const int bb = bh / NHEAD, hh = bh % NHEAD;
    #pragma unroll
    for (int mt = 0; mt < 2; mt++) {
        float a = lA[mt], b2 = lB[mt];
        a  += __shfl_xor_sync(0xffffffffu, a, 1);
        a  += __shfl_xor_sync(0xffffffffu, a, 2);
        b2 += __shfl_xor_sync(0xffffffffu, b2, 1);
        b2 += __shfl_xor_sync(0xffffffffu, b2, 2);
        const float ia = 1.f / a, ib = 1.f / b2;
        const int rA = n0 + w * 32 + mt * 16 + g;
        const size_t baseA = ((size_t)(bb * NN) + rA) * CDIM + hh * DHEAD;
        const size_t baseB = baseA + (size_t)8 * CDIM;
        #pragma unroll
        for (int nt = 0; nt < 4; nt++) {
            int col = nt * 8 + t4 * 2;
            uint32_t h0, l0, h1, l1;
            split2(of[mt][nt][0] * ia, of[mt][nt][1] * ia, h0, l0);
            split2(of[mt][nt][2] * ib, of[mt][nt][3] * ib, h1, l1);
            *(uint32_t*)(g_aoh + baseA + col) = h0;
            *(uint32_t*)(g_aol + baseA + col) = l0;
            *(uint32_t*)(g_aoh + baseB + col) = h1;
            *(uint32_t*)(g_aol + baseB + col) = l1;
        }
    }
}

// ---------------------------------------------------------------------------
// Kernel 3: projection GEMM on mma.sync bf16x3 + bias (R8 static version).
// ---------------------------------------------------------------------------
__global__ __launch_bounds__(256) void proj_mma(const float* __restrict__ bias,
                                                float* __restrict__ out) {
    __shared__ __align__(16) char sAh[128 * GROWB], sAl[128 * GROWB];
    __shared__ __align__(16) char sBh[128 * GROWB], sBl[128 * GROWB];

    const int tid  = threadIdx.x;
    const int w    = tid >> 5, lane = tid & 31;
    const int mw   = w & 1,   ow   = w >> 1;
    const int m0   = blockIdx.x * 128;
    const int o0   = blockIdx.y * 128;
    const int b    = m0 >> 10;

    const uint32_t ah_s = smem_u32(sAh), al_s = smem_u32(sAl);
    const uint32_t bh_s = smem_u32(sBh), bl_s = smem_u32(sBl);

    float acc[4][4][4];
    #pragma unroll
    for (int mt = 0; mt < 4; mt++)
        #pragma unroll
        for (int nt = 0; nt < 4; nt++)
            #pragma unroll
            for (int e = 0; e < 4; e++) acc[mt][nt][e] = 0.f;

    for (int it = 0; it < CDIM / 32; it++) {
        const int k0 = it * 32;
        __syncthreads();
        #pragma unroll
        for (int r = 0; r < 2; r++) {
            int idx = tid + 256 * r;
            int row = idx >> 2, c4 = idx & 3;
            size_t ga = (size_t)(m0 + row) * CDIM + k0 + c4 * 8;
            size_t gb = (size_t)(o0 + row) * CDIM + k0 + c4 * 8;
            *(uint4*)(sAh + row * GROWB + c4 * 16) = *(const uint4*)(g_aoh + ga);
            *(uint4*)(sAl + row * GROWB + c4 * 16) = *(const uint4*)(g_aol + ga);
            *(uint4*)(sBh + row * GROWB + c4 * 16) = *(const uint4*)(g_pwh + gb);
            *(uint4*)(sBl + row * GROWB + c4 * 16) = *(const uint4*)(g_pwl + gb);
        }
        __syncthreads();

        #pragma unroll
        for (int ks = 0; ks < 2; ks++) {
            uint32_t ah[4][4], al[4][4];
            const uint32_t aoff = (uint32_t)((mw * 64 + (lane & 15)) * GROWB
                                             + (ks * 16 + (lane >> 4) * 8) * 2);
            #pragma unroll
            for (int mt = 0; mt < 4; mt++) {
                LDMX4(ah[mt], ah_s + aoff + mt * 16 * GROWB);
                LDMX4(al[mt], al_s + aoff + mt * 16 * GROWB);
            }
            const uint32_t boff = (uint32_t)((ow * 32 + (lane & 7)) * GROWB
                                             + (ks * 16 + ((lane >> 3) & 1) * 8) * 2);
            #pragma unroll
            for (int nt = 0; nt < 4; nt++) {
                uint32_t b0, b1, c0r, c1;
                LDMX2(b0, b1, bh_s + boff + nt * 8 * GROWB);
                LDMX2(c0r, c1, bl_s + boff + nt * 8 * GROWB);
                #pragma unroll
                for (int mt = 0; mt < 4; mt++) {
                    mma_bf16(acc[mt][nt], ah[mt], b0, b1);
                    mma_bf16(acc[mt][nt], ah[mt], c0r, c1);
                    mma_bf16(acc[mt][nt], al[mt], b0, b1);
                }
            }
        }
    }

    // Epilogue: out[b][o][n] = acc + bias[o]
    const int g = lane >> 2, t4 = lane & 3;
    #pragma unroll
    for (int nt = 0; nt < 4; nt++) {
        const int o = o0 + ow * 32 + nt * 8 + t4 * 2;
        const float b0v = bias[o], b1v = bias[o + 1];
        float* r0 = out + ((size_t)b * CDIM + o) * NN;
        float* r1 = r0 + NN;
        #pragma unroll
        for (int mt = 0; mt < 4; mt++) {
            const int n = (m0 + mw * 64 + mt * 16 + g) & (NN - 1);
            float* ac = acc[mt][nt];
            r0[n]     = ac[0] + b0v;
            r1[n]     = ac[1] + b1v;
            r0[n + 8] = ac[2] + b0v;
            r1[n + 8] = ac[3] + b1v;
        }
    }
}

// ---------------------------------------------------------------------------
extern "C" void kernel_launch(void* const* d_in, const int* in_sizes, int n_in,
                              void* d_out, int out_size) {
    const float* x      = (const float*)d_in[0];   // [16,384,32,32]
    const float* qkv_w  = (const float*)d_in[1];   // [1152,384]
    const float* proj_w = (const float*)d_in[2];   // [384,384]
    const float* proj_b = (const float*)d_in[3];   // [384]
    float* out = (float*)d_out;                    // [16,384,32,32]

    convert_x<<<dim3(NN / 32, CDIM / 32, NB), dim3(32, 8)>>>(x);
    convert_w<<<(3 * CDIM * CDIM + 255) / 256, 256>>>(qkv_w, proj_w);
    qkv_mma<<<dim3(MT / 128, (3 * CDIM) / 128), 256>>>();
    attn_mma<<<dim3(NN / 128, NB * NHEAD), 128>>>();
    proj_mma<<<dim3(MT / 128, CDIM / 128), 256>>>(proj_b, out);
}

// round 13
// speedup vs baseline: 1.2806x; 1.0310x over previous
#include <cuda_runtime.h>
#include <cuda_bf16.h>
#include <cuda_fp16.h>
#include <cstdint>

// Problem constants
constexpr int CDIM  = 384;
constexpr int NHEAD = 12;
constexpr int DHEAD = 32;
constexpr int NB    = 16;
constexpr int NN    = 1024;            // 32*32 tokens
constexpr int MT    = NB * NN;         // 16384 rows
constexpr float QK_SCALE = 0.17677669529663687f; // 32^-0.5
constexpr float LOG2E    = 1.4426950408889634f;
constexpr float QS2      = QK_SCALE * LOG2E;     // folded into K at qkv epilogue

// Scratch (static device globals; no runtime allocation)
__device__ float          g_q [(size_t)NB * NHEAD * NN * DHEAD];  // fp32 Q
__device__ __half         g_k [(size_t)NB * NHEAD * NN * DHEAD];  // fp16 K (pre-scaled)
__device__ __half         g_v [(size_t)NB * NHEAD * NN * DHEAD];  // fp16 V (single)
__device__ __nv_bfloat16  g_xh[(size_t)MT * CDIM];   // x transposed [m][k]
__device__ __nv_bfloat16  g_xl[(size_t)MT * CDIM];
__device__ __nv_bfloat16  g_wh[(size_t)3 * CDIM * CDIM];   // qkv_w [o][k]
__device__ __nv_bfloat16  g_wl[(size_t)3 * CDIM * CDIM];
__device__ __nv_bfloat16  g_pwh[(size_t)CDIM * CDIM];      // proj_w [o][k]
__device__ __nv_bfloat16  g_pwl[(size_t)CDIM * CDIM];
__device__ __nv_bfloat16  g_aoh[(size_t)MT * CDIM];  // attention out [m][c]
__device__ __nv_bfloat16  g_aol[(size_t)MT * CDIM];

// ===========================================================================
// Helpers
// ===========================================================================
__device__ __forceinline__ float ex2f(float x) {
    float y; asm("ex2.approx.ftz.f32 %0, %1;" : "=f"(y) : "f"(x)); return y;
}
__device__ __forceinline__ void split1(float a, __nv_bfloat16& h, __nv_bfloat16& l) {
    h = __float2bfloat16(a);
    l = __float2bfloat16(a - __bfloat162float(h));
}
// bf16 pair split (GEMM path)
__device__ __forceinline__ void split2(float a, float b, uint32_t& hi, uint32_t& lo) {
    __nv_bfloat16 ah = __float2bfloat16(a), bh = __float2bfloat16(b);
    float ar = a - __bfloat162float(ah), br = b - __bfloat162float(bh);
    __nv_bfloat162 H = __halves2bfloat162(ah, bh);
    __nv_bfloat162 L = __halves2bfloat162(__float2bfloat16(ar), __float2bfloat16(br));
    hi = *(uint32_t*)&H; lo = *(uint32_t*)&L;
}
// fp16 pair split (attention Q path)
__device__ __forceinline__ void split2h(float a, float b, uint32_t& hi, uint32_t& lo) {
    __half ah = __float2half_rn(a), bh = __float2half_rn(b);
    float ar = a - __half2float(ah), br = b - __half2float(bh);
    __half2 H = __halves2half2(ah, bh);
    __half2 L = __halves2half2(__float2half_rn(ar), __float2half_rn(br));
    hi = *(uint32_t*)&H; lo = *(uint32_t*)&L;
}
__device__ __forceinline__ uint32_t pack_h2(float a, float b) {
    __half2 h = __floats2half2_rn(a, b);
    return *(uint32_t*)&h;
}
__device__ __forceinline__ uint32_t smem_u32(const void* p) {
    uint32_t a;
    asm("{ .reg .u64 t; cvta.to.shared.u64 t, %1; cvt.u32.u64 %0, t; }"
        : "=r"(a) : "l"(p));
    return a;
}
#define LDMX2(r0, r1, addr) \
    asm volatile("ldmatrix.sync.aligned.m8n8.x2.shared.b16 {%0,%1}, [%2];" \
                 : "=r"(r0), "=r"(r1) : "r"(addr))
#define LDMX2T(r0, r1, addr) \
    asm volatile("ldmatrix.sync.aligned.m8n8.x2.trans.shared.b16 {%0,%1}, [%2];" \
                 : "=r"(r0), "=r"(r1) : "r"(addr))
#define LDMX4(r, addr) \
    asm volatile("ldmatrix.sync.aligned.m8n8.x4.shared.b16 {%0,%1,%2,%3}, [%4];" \
                 : "=r"((r)[0]), "=r"((r)[1]), "=r"((r)[2]), "=r"((r)[3]) : "r"(addr))
__device__ __forceinline__ void mma_bf16(float* d, const uint32_t* a,
                                         uint32_t b0, uint32_t b1) {
    asm volatile(
        "mma.sync.aligned.m16n8k16.row.col.f32.bf16.bf16.f32 "
        "{%0,%1,%2,%3}, {%4,%5,%6,%7}, {%8,%9}, {%0,%1,%2,%3};"
        : "+f"(d[0]), "+f"(d[1]), "+f"(d[2]), "+f"(d[3])
        : "r"(a[0]), "r"(a[1]), "r"(a[2]), "r"(a[3]), "r"(b0), "r"(b1));
}
__device__ __forceinline__ void mma_f16(float* d, const uint32_t* a,
                                        uint32_t b0, uint32_t b1) {
    asm volatile(
        "mma.sync.aligned.m16n8k16.row.col.f32.f16.f16.f32 "
        "{%0,%1,%2,%3}, {%4,%5,%6,%7}, {%8,%9}, {%0,%1,%2,%3};"
        : "+f"(d[0]), "+f"(d[1]), "+f"(d[2]), "+f"(d[3])
        : "r"(a[0]), "r"(a[1]), "r"(a[2]), "r"(a[3]), "r"(b0), "r"(b1));
}
#define CP_ASYNC16(saddr, gptr) \
    asm volatile("cp.async.ca.shared.global [%0], [%1], 16;" \
                 :: "r"(saddr), "l"(gptr) : "memory")
#define CP_COMMIT() asm volatile("cp.async.commit_group;" ::: "memory")
#define CP_WAIT(n)  asm volatile("cp.async.wait_group %0;" :: "n"(n) : "memory")

// ---------------------------------------------------------------------------
// Kernel 0a: transpose+split x [b,c,n] fp32  ->  g_xh/g_xl [m=b*NN+n][k=c] bf16
// ---------------------------------------------------------------------------
__global__ __launch_bounds__(256) void convert_x(const float* __restrict__ x) {
    __shared__ float tile[32][33];
    const int b  = blockIdx.z;
    const int n0 = blockIdx.x * 32;
    const int c0 = blockIdx.y * 32;
    const int tx = threadIdx.x, ty = threadIdx.y;   // (32, 8)
    #pragma unroll
    for (int j = 0; j < 4; j++) {
        int c = c0 + ty + j * 8;
        tile[ty + j * 8][tx] = x[((size_t)b * CDIM + c) * NN + n0 + tx];
    }
    __syncthreads();
    #pragma unroll
    for (int j = 0; j < 4; j++) {
        int n = n0 + ty + j * 8;
        float v = tile[tx][ty + j * 8];
        __nv_bfloat16 h, l; split1(v, h, l);
        size_t idx = ((size_t)b * NN + n) * CDIM + c0 + tx;
        g_xh[idx] = h; g_xl[idx] = l;
    }
}

// ---------------------------------------------------------------------------
// Kernel 0b: split weights (qkv_w and proj_w) into bf16 hi/lo.
// ---------------------------------------------------------------------------
__global__ __launch_bounds__(256) void convert_w(const float* __restrict__ qkv_w,
                                                 const float* __restrict__ proj_w) {
    const int i = blockIdx.x * 256 + threadIdx.x;
    const int NW = 3 * CDIM * CDIM;
    if (i < NW) {
        __nv_bfloat16 h, l; split1(qkv_w[i], h, l);
        g_wh[i] = h; g_wl[i] = l;
    }
    if (i < CDIM * CDIM) {
        __nv_bfloat16 h, l; split1(proj_w[i], h, l);
        g_pwh[i] = h; g_pwl[i] = l;
    }
}

// ---------------------------------------------------------------------------
// Shared pipelined GEMM geometry (k-step 16, double-buffered)
// ---------------------------------------------------------------------------
constexpr int G2ROWB = 48;               // 16 elems * 2B = 32B data + 16B pad
constexpr int G2ARR  = 128 * G2ROWB;     // one 128-row k16 array (6144 B)
constexpr int G2STG  = 4 * G2ARR;        // stage: [Ah | Al | Bh | Bl] (24576 B)
constexpr int G2SMEM = 2 * G2STG;        // 49152 B dynamic

// ---------------------------------------------------------------------------
// Kernel 1: QKV GEMM, bf16x3 mma.sync, k16 cp.async double-buffered.
// C[m][o] = sum_k xT[m][k] * w[o][k].  Block 128m x 128o, 8 warps.
// Epilogue: Q fp32; K fp16 single scaled by QS2; V fp16 single.
// ---------------------------------------------------------------------------
__global__ __launch_bounds__(256) void qkv_mma() {
    extern __shared__ __align__(16) char dsm[];
    const uint32_t sb = smem_u32(dsm);

    const int tid  = threadIdx.x;
    const int w    = tid >> 5, lane = tid & 31;
    const int mw   = w & 1,   ow   = w >> 1;      // warp tile: 64m x 32o
    const int m0   = blockIdx.x * 128;
    const int o0   = blockIdx.y * 128;
    const int b    = m0 >> 10;

    const int lrow = tid >> 1, lc = tid & 1;       // 256 slots per array
    const uint32_t ld = (uint32_t)(lrow * G2ROWB + lc * 16);

    float acc[4][4][4];
    #pragma unroll
    for (int mt = 0; mt < 4; mt++)
        #pragma unroll
        for (int nt = 0; nt < 4; nt++)
            #pragma unroll
            for (int e = 0; e < 4; e++) acc[mt][nt][e] = 0.f;

    // ---- prologue: chunk 0 into stage 0 ----
    {
        size_t ga = (size_t)(m0 + lrow) * CDIM + lc * 8;
        size_t gb = (size_t)(o0 + lrow) * CDIM + lc * 8;
        CP_ASYNC16(sb + ld,             g_xh + ga);
        CP_ASYNC16(sb + G2ARR + ld,     g_xl + ga);
        CP_ASYNC16(sb + 2 * G2ARR + ld, g_wh + gb);
        CP_ASYNC16(sb + 3 * G2ARR + ld, g_wl + gb);
        CP_COMMIT();
    }

    constexpr int NIT = CDIM / 16;   // 24
    for (int it = 0; it < NIT; it++) {
        if (it + 1 < NIT) {
            const uint32_t nsb = sb + (uint32_t)((it + 1) & 1) * G2STG;
            const int k0 = (it + 1) * 16;
            size_t ga = (size_t)(m0 + lrow) * CDIM + k0 + lc * 8;
            size_t gb = (size_t)(o0 + lrow) * CDIM + k0 + lc * 8;
            CP_ASYNC16(nsb + ld,             g_xh + ga);
            CP_ASYNC16(nsb + G2ARR + ld,     g_xl + ga);
            CP_ASYNC16(nsb + 2 * G2ARR + ld, g_wh + gb);
            CP_ASYNC16(nsb + 3 * G2ARR + ld, g_wl + gb);
            CP_COMMIT();
            CP_WAIT(1);
        } else {
            CP_WAIT(0);
        }
        __syncthreads();

        const uint32_t cb   = sb + (uint32_t)(it & 1) * G2STG;
        const uint32_t ah_s = cb,             al_s = cb + G2ARR;
        const uint32_t bh_s = cb + 2 * G2ARR, bl_s = cb + 3 * G2ARR;

        uint32_t ah[4][4], al[4][4];
        const uint32_t aoff = (uint32_t)((mw * 64 + (lane & 15)) * G2ROWB
                                         + (lane >> 4) * 16);
        #pragma unroll
        for (int mt = 0; mt < 4; mt++) {
            LDMX4(ah[mt], ah_s + aoff + mt * 16 * G2ROWB);
            LDMX4(al[mt], al_s + aoff + mt * 16 * G2ROWB);
        }
        const uint32_t boff = (uint32_t)((ow * 32 + (lane & 7)) * G2ROWB
                                         + ((lane >> 3) & 1) * 16);
        #pragma unroll
        for (int nt = 0; nt < 4; nt++) {
            uint32_t b0, b1, c0r, c1;
            LDMX2(b0, b1, bh_s + boff + nt * 8 * G2ROWB);
            LDMX2(c0r, c1, bl_s + boff + nt * 8 * G2ROWB);
            #pragma unroll
            for (int mt = 0; mt < 4; mt++) {
                mma_bf16(acc[mt][nt], ah[mt], b0, b1);
                mma_bf16(acc[mt][nt], ah[mt], c0r, c1);
                mma_bf16(acc[mt][nt], al[mt], b0, b1);
            }
        }
        __syncthreads();
    }

    // Epilogue: Q -> fp32; K -> fp16 (scaled); V -> fp16 single.
    const int g = lane >> 2, t4 = lane & 3;
    #pragma unroll
    for (int mt = 0; mt < 4; mt++) {
        const int n = (m0 + mw * 64 + mt * 16 + g) & (NN - 1);
        #pragma unroll
        for (int nt = 0; nt < 4; nt++) {
            const int o   = o0 + ow * 32 + nt * 8 + t4 * 2;
            const int wch = o / CDIM;
            const int rem = o % CDIM;
            const int h   = rem >> 5, d = rem & 31;
            const size_t base0 = ((size_t)(b * NHEAD + h) * NN + n) * DHEAD + d;
            const size_t base1 = base0 + 8 * DHEAD;   // row n+8
            float* ac = acc[mt][nt];
            if (wch == 0) {
                *(float2*)(g_q + base0) = make_float2(ac[0], ac[1]);
                *(float2*)(g_q + base1) = make_float2(ac[2], ac[3]);
            } else if (wch == 1) {
                *(uint32_t*)(g_k + base0) = pack_h2(ac[0] * QS2, ac[1] * QS2);
                *(uint32_t*)(g_k + base1) = pack_h2(ac[2] * QS2, ac[3] * QS2);
            } else {
                *(uint32_t*)(g_v + base0) = pack_h2(ac[0], ac[1]);
                *(uint32_t*)(g_v + base1) = pack_h2(ac[2], ac[3]);
            }
        }
    }
}

// ---------------------------------------------------------------------------
// Kernel 2: flash attention, fp16 mma.sync.
//   S = (qh+ql) . k_fp16   (2 terms; K pre-scaled by QS2)
//   P = fp16(exp2(S))
//   O += P . v_fp16        (1 term)
// 4 warps x 32 query rows; cp.async double buffering; 16 chunks of 64 keys.
// ---------------------------------------------------------------------------
constexpr int ROWB = 80;

__global__ __launch_bounds__(128, 4) void attn_mma() {
    __shared__ __align__(16) char sk[2][64 * ROWB];
    __shared__ __align__(16) char sv[2][64 * ROWB];

    const int tid = threadIdx.x;
    const int w   = tid >> 5;
    const int l   = tid & 31;
    const int g   = l >> 2;
    const int t4  = l & 3;
    const int lane = l & 15;
    const int bh  = blockIdx.y;
    const int n0  = blockIdx.x * 128;

    const uint32_t sk0 = smem_u32(sk[0]);
    const uint32_t sv0 = smem_u32(sv[0]);
    constexpr uint32_t BUFB = 64 * ROWB;

    // ---- per-thread chunk-load geometry ----
    const int    ldrow = tid >> 2, ldc4 = tid & 3;
    const size_t ldsrc0 = ((size_t)bh * NN + ldrow) * DHEAD + ldc4 * 8;
    const uint32_t lddst = (uint32_t)(ldrow * ROWB + ldc4 * 16);
    const size_t ldsrc1 = ldsrc0 + (size_t)32 * DHEAD;
    const uint32_t lddst1 = lddst + 32 * ROWB;

    // ---- prologue: async-load chunk 0 into buffer 0 ----
    CP_ASYNC16(sk0 + lddst,  g_k + ldsrc0);
    CP_ASYNC16(sk0 + lddst1, g_k + ldsrc1);
    CP_ASYNC16(sv0 + lddst,  g_v + ldsrc0);
    CP_ASYNC16(sv0 + lddst1, g_v + ldsrc1);
    CP_COMMIT();

    // ---- Q fragments: fp16 hi/lo split, NO scale (folded into K) ----
    uint32_t qh[2][2][4], ql[2][2][4];
    {
        const float* qb = g_q + ((size_t)bh * NN + n0 + w * 32) * DHEAD;
        #pragma unroll
        for (int mt = 0; mt < 2; mt++)
            #pragma unroll
            for (int ks = 0; ks < 2; ks++) {
                int rA = mt * 16 + g, rB = rA + 8, kk = ks * 16 + t4 * 2;
                float2 v0 = *(const float2*)(qb + rA * DHEAD + kk);
                float2 v1 = *(const float2*)(qb + rB * DHEAD + kk);
                float2 v2 = *(const float2*)(qb + rA * DHEAD + kk + 8);
                float2 v3 = *(const float2*)(qb + rB * DHEAD + kk + 8);
                split2h(v0.x, v0.y, qh[mt][ks][0], ql[mt][ks][0]);
                split2h(v1.x, v1.y, qh[mt][ks][1], ql[mt][ks][1]);
                split2h(v2.x, v2.y, qh[mt][ks][2], ql[mt][ks][2]);
                split2h(v3.x, v3.y, qh[mt][ks][3], ql[mt][ks][3]);
            }
    }

    float of[2][4][4];
    #pragma unroll
    for (int mt = 0; mt < 2; mt++)
        #pragma unroll
        for (int nt = 0; nt < 4; nt++)
            #pragma unroll
            for (int e = 0; e < 4; e++) of[mt][nt][e] = 0.f;

    float lA[2] = {0.f, 0.f}, lB[2] = {0.f, 0.f};

    for (int it = 0; it < 16; it++) {
        const uint32_t bofs = (uint32_t)(it & 1) * BUFB;
        if (it < 15) {
            const uint32_t nofs = (uint32_t)((it + 1) & 1) * BUFB;
            const size_t koff = (size_t)(it + 1) * 64 * DHEAD;
            CP_ASYNC16(sk0 + nofs + lddst,  g_k + ldsrc0 + koff);
            CP_ASYNC16(sk0 + nofs + lddst1, g_k + ldsrc1 + koff);
            CP_ASYNC16(sv0 + nofs + lddst,  g_v + ldsrc0 + koff);
            CP_ASYNC16(sv0 + nofs + lddst1, g_v + ldsrc1 + koff);
            CP_COMMIT();
            CP_WAIT(1);
        } else {
            CP_WAIT(0);
        }
        __syncthreads();

        // ---- interleaved: per 16-key group: S-mma -> exp -> pack -> PV ----
        #pragma unroll
        for (int s = 0; s < 4; s++) {
            uint32_t pfh[2][4];   // fp16 A-fragments of P for this key group
            #pragma unroll
            for (int hhf = 0; hhf < 2; hhf++) {
                const int nt = 2 * s + hhf;
                float sf[2][4];
                #pragma unroll
                for (int mt = 0; mt < 2; mt++)
                    #pragma unroll
                    for (int e = 0; e < 4; e++) sf[mt][e] = 0.f;
                #pragma unroll
                for (int ks = 0; ks < 2; ks++) {
                    uint32_t aoff = bofs + (uint32_t)((nt * 8 + (lane & 7)) * ROWB
                                               + (ks * 16 + (lane >> 3) * 8) * 2);
                    uint32_t k0f, k1f;
                    LDMX2(k0f, k1f, sk0 + aoff);
                    #pragma unroll
                    for (int mt = 0; mt < 2; mt++) {
                        mma_f16(sf[mt], qh[mt][ks], k0f, k1f);
                        mma_f16(sf[mt], ql[mt][ks], k0f, k1f);
                    }
                }
                #pragma unroll
                for (int mt = 0; mt < 2; mt++) {
                    float p0 = ex2f(sf[mt][0]);
                    float p1 = ex2f(sf[mt][1]);
                    float p2 = ex2f(sf[mt][2]);
                    float p3 = ex2f(sf[mt][3]);
                    lA[mt] += p0 + p1;
                    lB[mt] += p2 + p3;
                    pfh[mt][hhf * 2]     = pack_h2(p0, p1);
                    pfh[mt][hhf * 2 + 1] = pack_h2(p2, p3);
                }
            }
            // ---- O += P.v for keys [s*16, s*16+16) ----
            #pragma unroll
            for (int nt = 0; nt < 4; nt++) {
                uint32_t voff = bofs + (uint32_t)((s * 16 + lane) * ROWB + nt * 16);
                uint32_t v0f, v1f;
                LDMX2T(v0f, v1f, sv0 + voff);
                #pragma unroll
                for (int mt = 0; mt < 2; mt++)
                    mma_f16(of[mt][nt], pfh[mt], v0f, v1f);
            }
        }
        __syncthreads();
    }

    // ---- normalize + write g_aoh/g_aol [m][c] (bf16 hi/lo for proj) ----
    const int bb = bh / NHEAD, hh = bh % NHEAD;
    #pragma unroll
    for (int mt = 0; mt < 2; mt++) {
        float a = lA[mt], b2 = lB[mt];
        a  += __shfl_xor_sync(0xffffffffu, a, 1);
        a  += __shfl_xor_sync(0xffffffffu, a, 2);
        b2 += __shfl_xor_sync(0xffffffffu, b2, 1);
        b2 += __shfl_xor_sync(0xffffffffu, b2, 2);
        const float ia = 1.f / a, ib = 1.f / b2;
        const int rA = n0 + w * 32 + mt * 16 + g;
        const size_t baseA = ((size_t)(bb * NN) + rA) * CDIM + hh * DHEAD;
        const size_t baseB = baseA + (size_t)8 * CDIM;
        #pragma unroll
        for (int nt = 0; nt < 4; nt++) {
            int col = nt * 8 + t4 * 2;
            uint32_t h0, l0, h1, l1;
            split2(of[mt][nt][0] * ia, of[mt][nt][1] * ia, h0, l0);
            split2(of[mt][nt][2] * ib, of[mt][nt][3] * ib, h1, l1);
            *(uint32_t*)(g_aoh + baseA + col) = h0;
            *(uint32_t*)(g_aol + baseA + col) = l0;
            *(uint32_t*)(g_aoh + baseB + col) = h1;
            *(uint32_t*)(g_aol + baseB + col) = l1;
        }
    }
}

// ---------------------------------------------------------------------------
// Kernel 3: projection GEMM, bf16x3 mma.sync + bias, k16 pipelined.
// ---------------------------------------------------------------------------
__global__ __launch_bounds__(256) void proj_mma(const float* __restrict__ bias,
                                                float* __restrict__ out) {
    extern __shared__ __align__(16) char dsm[];
    const uint32_t sb = smem_u32(dsm);

    const int tid  = threadIdx.x;
    const int w    = tid >> 5, lane = tid & 31;
    const int mw   = w & 1,   ow   = w >> 1;
    const int m0   = blockIdx.x * 128;
    const int o0   = blockIdx.y * 128;
    const int b    = m0 >> 10;

    const int lrow = tid >> 1, lc = tid & 1;
    const uint32_t ld = (uint32_t)(lrow * G2ROWB + lc * 16);

    float acc[4][4][4];
    #pragma unroll
    for (int mt = 0; mt < 4; mt++)
        #pragma unroll
        for (int nt = 0; nt < 4; nt++)
            #pragma unroll
            for (int e = 0; e < 4; e++) acc[mt][nt][e] = 0.f;

    {
        size_t ga = (size_t)(m0 + lrow) * CDIM + lc * 8;
        size_t gb = (size_t)(o0 + lrow) * CDIM + lc * 8;
        CP_ASYNC16(sb + ld,             g_aoh + ga);
        CP_ASYNC16(sb + G2ARR + ld,     g_aol + ga);
        CP_ASYNC16(sb + 2 * G2ARR + ld, g_pwh + gb);
        CP_ASYNC16(sb + 3 * G2ARR + ld, g_pwl + gb);
        CP_COMMIT();
    }

    constexpr int NIT = CDIM / 16;
    for (int it = 0; it < NIT; it++) {
        if (it + 1 < NIT) {
            const uint32_t nsb = sb + (uint32_t)((it + 1) & 1) * G2STG;
            const int k0 = (it + 1) * 16;
            size_t ga = (size_t)(m0 + lrow) * CDIM + k0 + lc * 8;
            size_t gb = (size_t)(o0 + lrow) * CDIM + k0 + lc * 8;
            CP_ASYNC16(nsb + ld,             g_aoh + ga);
            CP_ASYNC16(nsb + G2ARR + ld,     g_aol + ga);
            CP_ASYNC16(nsb + 2 * G2ARR + ld, g_pwh + gb);
            CP_ASYNC16(nsb + 3 * G2ARR + ld, g_pwl + gb);
            CP_COMMIT();
            CP_WAIT(1);
        } else {
            CP_WAIT(0);
        }
        __syncthreads();

        const uint32_t cb   = sb + (uint32_t)(it & 1) * G2STG;
        const uint32_t ah_s = cb,             al_s = cb + G2ARR;
        const uint32_t bh_s = cb + 2 * G2ARR, bl_s = cb + 3 * G2ARR;

        uint32_t ah[4][4], al[4][4];
        const uint32_t aoff = (uint32_t)((mw * 64 + (lane & 15)) * G2ROWB
                                         + (lane >> 4) * 16);
        #pragma unroll
        for (int mt = 0; mt < 4; mt++) {
            LDMX4(ah[mt], ah_s + aoff + mt * 16 * G2ROWB);
            LDMX4(al[mt], al_s + aoff + mt * 16 * G2ROWB);
        }
        const uint32_t boff = (uint32_t)((ow * 32 + (lane & 7)) * G2ROWB
                                         + ((lane >> 3) & 1) * 16);
        #pragma unroll
        for (int nt = 0; nt < 4; nt++) {
            uint32_t b0, b1, c0r, c1;
            LDMX2(b0, b1, bh_s + boff + nt * 8 * G2ROWB);
            LDMX2(c0r, c1, bl_s + boff + nt * 8 * G2ROWB);
            #pragma unroll
            for (int mt = 0; mt < 4; mt++) {
                mma_bf16(acc[mt][nt], ah[mt], b0, b1);
                mma_bf16(acc[mt][nt], ah[mt], c0r, c1);
                mma_bf16(acc[mt][nt], al[mt], b0, b1);
            }
        }
        __syncthreads();
    }

    // Epilogue: out[b][o][n] = acc + bias[o]
    const int g = lane >> 2, t4 = lane & 3;
    #pragma unroll
    for (int nt = 0; nt < 4; nt++) {
        const int o = o0 + ow * 32 + nt * 8 + t4 * 2;
        const float b0v = bias[o], b1v = bias[o + 1];
        float* r0 = out + ((size_t)b * CDIM + o) * NN;
        float* r1 = r0 + NN;
        #pragma unroll
        for (int mt = 0; mt < 4; mt++) {
            const int n = (m0 + mw * 64 + mt * 16 + g) & (NN - 1);
            float* ac = acc[mt][nt];
            r0[n]     = ac[0] + b0v;
            r1[n]     = ac[1] + b1v;
            r0[n + 8] = ac[2] + b0v;
            r1[n + 8] = ac[3] + b1v;
        }
    }
}

// ---------------------------------------------------------------------------
extern "C" void kernel_launch(void* const* d_in, const int* in_sizes, int n_in,
                              void* d_out, int out_size) {
    const float* x      = (const float*)d_in[0];   // [16,384,32,32]
    const float* qkv_w  = (const float*)d_in[1];   // [1152,384]
    const float* proj_w = (const float*)d_in[2];   // [384,384]
    const float* proj_b = (const float*)d_in[3];   // [384]
    float* out = (float*)d_out;                    // [16,384,32,32]

    cudaFuncSetAttribute(qkv_mma,  cudaFuncAttributeMaxDynamicSharedMemorySize, G2SMEM);
    cudaFuncSetAttribute(proj_mma, cudaFuncAttributeMaxDynamicSharedMemorySize, G2SMEM);

    convert_x<<<dim3(NN / 32, CDIM / 32, NB), dim3(32, 8)>>>(x);
    convert_w<<<(3 * CDIM * CDIM + 255) / 256, 256>>>(qkv_w, proj_w);
    qkv_mma<<<dim3(MT / 128, (3 * CDIM) / 128), 256, G2SMEM>>>();
    attn_mma<<<dim3(NN / 128, NB * NHEAD), 128>>>();
    proj_mma<<<dim3(MT / 128, CDIM / 128), 256, G2SMEM>>>(proj_b, out);
}

// round 14
// speedup vs baseline: 1.4901x; 1.1636x over previous
#include <cuda_runtime.h>
#include <cuda_bf16.h>
#include <cuda_fp16.h>
#include <cstdint>

// Problem constants
constexpr int CDIM  = 384;
constexpr int NHEAD = 12;
constexpr int DHEAD = 32;
constexpr int NB    = 16;
constexpr int NN    = 1024;            // 32*32 tokens
constexpr int MT    = NB * NN;         // 16384 rows
constexpr float QK_SCALE = 0.17677669529663687f; // 32^-0.5
constexpr float LOG2E    = 1.4426950408889634f;
constexpr float QS2      = QK_SCALE * LOG2E;     // folded into K at qkv epilogue

// Scratch (static device globals; no runtime allocation)
__device__ float          g_q [(size_t)NB * NHEAD * NN * DHEAD];  // fp32 Q
__device__ __half         g_k [(size_t)NB * NHEAD * NN * DHEAD];  // fp16 K (pre-scaled)
__device__ __half         g_v [(size_t)NB * NHEAD * NN * DHEAD];  // fp16 V (single)
__device__ __nv_bfloat16  g_xh[(size_t)MT * CDIM];   // x transposed [m][k]
__device__ __nv_bfloat16  g_xl[(size_t)MT * CDIM];
__device__ __nv_bfloat16  g_wh[(size_t)3 * CDIM * CDIM];   // qkv_w [o][k]
__device__ __nv_bfloat16  g_wl[(size_t)3 * CDIM * CDIM];
__device__ __nv_bfloat16  g_pwh[(size_t)CDIM * CDIM];      // proj_w [o][k]
__device__ __nv_bfloat16  g_pwl[(size_t)CDIM * CDIM];
__device__ __nv_bfloat16  g_aoh[(size_t)MT * CDIM];  // attention out [m][c]
__device__ __nv_bfloat16  g_aol[(size_t)MT * CDIM];

// ===========================================================================
// Helpers
// ===========================================================================
__device__ __forceinline__ float ex2f(float x) {
    float y; asm("ex2.approx.ftz.f32 %0, %1;" : "=f"(y) : "f"(x)); return y;
}
__device__ __forceinline__ void split1(float a, __nv_bfloat16& h, __nv_bfloat16& l) {
    h = __float2bfloat16(a);
    l = __float2bfloat16(a - __bfloat162float(h));
}
// bf16 pair split (GEMM path)
__device__ __forceinline__ void split2(float a, float b, uint32_t& hi, uint32_t& lo) {
    __nv_bfloat16 ah = __float2bfloat16(a), bh = __float2bfloat16(b);
    float ar = a - __bfloat162float(ah), br = b - __bfloat162float(bh);
    __nv_bfloat162 H = __halves2bfloat162(ah, bh);
    __nv_bfloat162 L = __halves2bfloat162(__float2bfloat16(ar), __float2bfloat16(br));
    hi = *(uint32_t*)&H; lo = *(uint32_t*)&L;
}
__device__ __forceinline__ uint32_t pack_h2(float a, float b) {
    __half2 h = __floats2half2_rn(a, b);
    return *(uint32_t*)&h;
}
__device__ __forceinline__ uint32_t smem_u32(const void* p) {
    uint32_t a;
    asm("{ .reg .u64 t; cvta.to.shared.u64 t, %1; cvt.u32.u64 %0, t; }"
        : "=r"(a) : "l"(p));
    return a;
}
#define LDMX2(r0, r1, addr) \
    asm volatile("ldmatrix.sync.aligned.m8n8.x2.shared.b16 {%0,%1}, [%2];" \
                 : "=r"(r0), "=r"(r1) : "r"(addr))
#define LDMX2T(r0, r1, addr) \
    asm volatile("ldmatrix.sync.aligned.m8n8.x2.trans.shared.b16 {%0,%1}, [%2];" \
                 : "=r"(r0), "=r"(r1) : "r"(addr))
#define LDMX4(r, addr) \
    asm volatile("ldmatrix.sync.aligned.m8n8.x4.shared.b16 {%0,%1,%2,%3}, [%4];" \
                 : "=r"((r)[0]), "=r"((r)[1]), "=r"((r)[2]), "=r"((r)[3]) : "r"(addr))
__device__ __forceinline__ void mma_bf16(float* d, const uint32_t* a,
                                         uint32_t b0, uint32_t b1) {
    asm volatile(
        "mma.sync.aligned.m16n8k16.row.col.f32.bf16.bf16.f32 "
        "{%0,%1,%2,%3}, {%4,%5,%6,%7}, {%8,%9}, {%0,%1,%2,%3};"
        : "+f"(d[0]), "+f"(d[1]), "+f"(d[2]), "+f"(d[3])
        : "r"(a[0]), "r"(a[1]), "r"(a[2]), "r"(a[3]), "r"(b0), "r"(b1));
}
__device__ __forceinline__ void mma_f16(float* d, const uint32_t* a,
                                        uint32_t b0, uint32_t b1) {
    asm volatile(
        "mma.sync.aligned.m16n8k16.row.col.f32.f16.f16.f32 "
        "{%0,%1,%2,%3}, {%4,%5,%6,%7}, {%8,%9}, {%0,%1,%2,%3};"
        : "+f"(d[0]), "+f"(d[1]), "+f"(d[2]), "+f"(d[3])
        : "r"(a[0]), "r"(a[1]), "r"(a[2]), "r"(a[3]), "r"(b0), "r"(b1));
}
#define CP_ASYNC16(saddr, gptr) \
    asm volatile("cp.async.ca.shared.global [%0], [%1], 16;" \
                 :: "r"(saddr), "l"(gptr) : "memory")
#define CP_COMMIT() asm volatile("cp.async.commit_group;" ::: "memory")
#define CP_WAIT(n)  asm volatile("cp.async.wait_group %0;" :: "n"(n) : "memory")

// ---------------------------------------------------------------------------
// Kernel 0a: transpose+split x [b,c,n] fp32  ->  g_xh/g_xl [m=b*NN+n][k=c] bf16
// ---------------------------------------------------------------------------
__global__ __launch_bounds__(256) void convert_x(const float* __restrict__ x) {
    __shared__ float tile[32][33];
    const int b  = blockIdx.z;
    const int n0 = blockIdx.x * 32;
    const int c0 = blockIdx.y * 32;
    const int tx = threadIdx.x, ty = threadIdx.y;   // (32, 8)
    #pragma unroll
    for (int j = 0; j < 4; j++) {
        int c = c0 + ty + j * 8;
        tile[ty + j * 8][tx] = x[((size_t)b * CDIM + c) * NN + n0 + tx];
    }
    __syncthreads();
    #pragma unroll
    for (int j = 0; j < 4; j++) {
        int n = n0 + ty + j * 8;
        float v = tile[tx][ty + j * 8];
        __nv_bfloat16 h, l; split1(v, h, l);
        size_t idx = ((size_t)b * NN + n) * CDIM + c0 + tx;
        g_xh[idx] = h; g_xl[idx] = l;
    }
}

// ---------------------------------------------------------------------------
// Kernel 0b: split weights (qkv_w and proj_w) into bf16 hi/lo.
// ---------------------------------------------------------------------------
__global__ __launch_bounds__(256) void convert_w(const float* __restrict__ qkv_w,
                                                 const float* __restrict__ proj_w) {
    const int i = blockIdx.x * 256 + threadIdx.x;
    const int NW = 3 * CDIM * CDIM;
    if (i < NW) {
        __nv_bfloat16 h, l; split1(qkv_w[i], h, l);
        g_wh[i] = h; g_wl[i] = l;
    }
    if (i < CDIM * CDIM) {
        __nv_bfloat16 h, l; split1(proj_w[i], h, l);
        g_pwh[i] = h; g_pwl[i] = l;
    }
}

// ---------------------------------------------------------------------------
// Kernel 1: QKV GEMM on mma.sync bf16x3 (static k32 mainloop, verified).
// Epilogue: Q fp32; K fp16 single scaled by QS2; V fp16 single.
// ---------------------------------------------------------------------------
constexpr int GROWB = 80;   // 32 elems * 2B = 64B data + 16B pad

__global__ __launch_bounds__(256) void qkv_mma() {
    __shared__ __align__(16) char sAh[128 * GROWB], sAl[128 * GROWB];
    __shared__ __align__(16) char sBh[128 * GROWB], sBl[128 * GROWB];

    const int tid  = threadIdx.x;
    const int w    = tid >> 5, lane = tid & 31;
    const int mw   = w & 1,   ow   = w >> 1;      // warp tile: 64m x 32o
    const int m0   = blockIdx.x * 128;
    const int o0   = blockIdx.y * 128;
    const int b    = m0 >> 10;

    const uint32_t ah_s = smem_u32(sAh), al_s = smem_u32(sAl);
    const uint32_t bh_s = smem_u32(sBh), bl_s = smem_u32(sBl);

    float acc[4][4][4];
    #pragma unroll
    for (int mt = 0; mt < 4; mt++)
        #pragma unroll
        for (int nt = 0; nt < 4; nt++)
            #pragma unroll
            for (int e = 0; e < 4; e++) acc[mt][nt][e] = 0.f;

    for (int it = 0; it < CDIM / 32; it++) {
        const int k0 = it * 32;
        __syncthreads();
        #pragma unroll
        for (int r = 0; r < 2; r++) {
            int idx = tid + 256 * r;
            int row = idx >> 2, c4 = idx & 3;
            size_t ga = (size_t)(m0 + row) * CDIM + k0 + c4 * 8;
            size_t gb = (size_t)(o0 + row) * CDIM + k0 + c4 * 8;
            *(uint4*)(sAh + row * GROWB + c4 * 16) = *(const uint4*)(g_xh + ga);
            *(uint4*)(sAl + row * GROWB + c4 * 16) = *(const uint4*)(g_xl + ga);
            *(uint4*)(sBh + row * GROWB + c4 * 16) = *(const uint4*)(g_wh + gb);
            *(uint4*)(sBl + row * GROWB + c4 * 16) = *(const uint4*)(g_wl + gb);
        }
        __syncthreads();

        #pragma unroll
        for (int ks = 0; ks < 2; ks++) {
            uint32_t ah[4][4], al[4][4];
            const uint32_t aoff = (uint32_t)((mw * 64 + (lane & 15)) * GROWB
                                             + (ks * 16 + (lane >> 4) * 8) * 2);
            #pragma unroll
            for (int mt = 0; mt < 4; mt++) {
                LDMX4(ah[mt], ah_s + aoff + mt * 16 * GROWB);
                LDMX4(al[mt], al_s + aoff + mt * 16 * GROWB);
            }
            const uint32_t boff = (uint32_t)((ow * 32 + (lane & 7)) * GROWB
                                             + (ks * 16 + ((lane >> 3) & 1) * 8) * 2);
            #pragma unroll
            for (int nt = 0; nt < 4; nt++) {
                uint32_t b0, b1, c0r, c1;
                LDMX2(b0, b1, bh_s + boff + nt * 8 * GROWB);
                LDMX2(c0r, c1, bl_s + boff + nt * 8 * GROWB);
                #pragma unroll
                for (int mt = 0; mt < 4; mt++) {
                    mma_bf16(acc[mt][nt], ah[mt], b0, b1);
                    mma_bf16(acc[mt][nt], ah[mt], c0r, c1);
                    mma_bf16(acc[mt][nt], al[mt], b0, b1);
                }
            }
        }
    }

    // Epilogue: Q -> fp32; K -> fp16 (scaled by QS2); V -> fp16 single.
    const int g = lane >> 2, t4 = lane & 3;
    #pragma unroll
    for (int mt = 0; mt < 4; mt++) {
        const int n = (m0 + mw * 64 + mt * 16 + g) & (NN - 1);
        #pragma unroll
        for (int nt = 0; nt < 4; nt++) {
            const int o   = o0 + ow * 32 + nt * 8 + t4 * 2;
            const int wch = o / CDIM;
            const int rem = o % CDIM;
            const int h   = rem >> 5, d = rem & 31;
            const size_t base0 = ((size_t)(b * NHEAD + h) * NN + n) * DHEAD + d;
            const size_t base1 = base0 + 8 * DHEAD;   // row n+8
            float* ac = acc[mt][nt];
            if (wch == 0) {
                *(float2*)(g_q + base0) = make_float2(ac[0], ac[1]);
                *(float2*)(g_q + base1) = make_float2(ac[2], ac[3]);
            } else if (wch == 1) {
                *(uint32_t*)(g_k + base0) = pack_h2(ac[0] * QS2, ac[1] * QS2);
                *(uint32_t*)(g_k + base1) = pack_h2(ac[2] * QS2, ac[3] * QS2);
            } else {
                *(uint32_t*)(g_v + base0) = pack_h2(ac[0], ac[1]);
                *(uint32_t*)(g_v + base1) = pack_h2(ac[2], ac[3]);
            }
        }
    }
}

// ---------------------------------------------------------------------------
// Kernel 2: flash attention, fp16 mma.sync, ALL single-precision fragments:
//   S = q_fp16 . k_fp16    (1 term; K pre-scaled by QS2)
//   P = fp16(exp2(S))
//   O += P . v_fp16        (1 term)
// 4 warps x 32 query rows; cp.async double buffering; 16 chunks of 64 keys.
// ---------------------------------------------------------------------------
constexpr int ROWB = 80;

__global__ __launch_bounds__(128, 4) void attn_mma() {
    __shared__ __align__(16) char sk[2][64 * ROWB];
    __shared__ __align__(16) char sv[2][64 * ROWB];

    const int tid = threadIdx.x;
    const int w   = tid >> 5;
    const int l   = tid & 31;
    const int g   = l >> 2;
    const int t4  = l & 3;
    const int lane = l & 15;
    const int bh  = blockIdx.y;
    const int n0  = blockIdx.x * 128;

    const uint32_t sk0 = smem_u32(sk[0]);
    const uint32_t sv0 = smem_u32(sv[0]);
    constexpr uint32_t BUFB = 64 * ROWB;

    // ---- per-thread chunk-load geometry ----
    const int    ldrow = tid >> 2, ldc4 = tid & 3;
    const size_t ldsrc0 = ((size_t)bh * NN + ldrow) * DHEAD + ldc4 * 8;
    const uint32_t lddst = (uint32_t)(ldrow * ROWB + ldc4 * 16);
    const size_t ldsrc1 = ldsrc0 + (size_t)32 * DHEAD;
    const uint32_t lddst1 = lddst + 32 * ROWB;

    // ---- prologue: async-load chunk 0 into buffer 0 ----
    CP_ASYNC16(sk0 + lddst,  g_k + ldsrc0);
    CP_ASYNC16(sk0 + lddst1, g_k + ldsrc1);
    CP_ASYNC16(sv0 + lddst,  g_v + ldsrc0);
    CP_ASYNC16(sv0 + lddst1, g_v + ldsrc1);
    CP_COMMIT();

    // ---- Q fragments: single fp16 (no scale; folded into K) ----
    uint32_t qh[2][2][4];
    {
        const float* qb = g_q + ((size_t)bh * NN + n0 + w * 32) * DHEAD;
        #pragma unroll
        for (int mt = 0; mt < 2; mt++)
            #pragma unroll
            for (int ks = 0; ks < 2; ks++) {
                int rA = mt * 16 + g, rB = rA + 8, kk = ks * 16 + t4 * 2;
                float2 v0 = *(const float2*)(qb + rA * DHEAD + kk);
                float2 v1 = *(const float2*)(qb + rB * DHEAD + kk);
                float2 v2 = *(const float2*)(qb + rA * DHEAD + kk + 8);
                float2 v3 = *(const float2*)(qb + rB * DHEAD + kk + 8);
                qh[mt][ks][0] = pack_h2(v0.x, v0.y);
                qh[mt][ks][1] = pack_h2(v1.x, v1.y);
                qh[mt][ks][2] = pack_h2(v2.x, v2.y);
                qh[mt][ks][3] = pack_h2(v3.x, v3.y);
            }
    }

    float of[2][4][4];
    #pragma unroll
    for (int mt = 0; mt < 2; mt++)
        #pragma unroll
        for (int nt = 0; nt < 4; nt++)
            #pragma unroll
            for (int e = 0; e < 4; e++) of[mt][nt][e] = 0.f;

    float lA[2] = {0.f, 0.f}, lB[2] = {0.f, 0.f};

    for (int it = 0; it < 16; it++) {
        const uint32_t bofs = (uint32_t)(it & 1) * BUFB;
        if (it < 15) {
            const uint32_t nofs = (uint32_t)((it + 1) & 1) * BUFB;
            const size_t koff = (size_t)(it + 1) * 64 * DHEAD;
            CP_ASYNC16(sk0 + nofs + lddst,  g_k + ldsrc0 + koff);
            CP_ASYNC16(sk0 + nofs + lddst1, g_k + ldsrc1 + koff);
            CP_ASYNC16(sv0 + nofs + lddst,  g_v + ldsrc0 + koff);
            CP_ASYNC16(sv0 + nofs + lddst1, g_v + ldsrc1 + koff);
            CP_COMMIT();
            CP_WAIT(1);
        } else {
            CP_WAIT(0);
        }
        __syncthreads();

        // ---- interleaved: per 16-key group: S-mma -> exp -> pack -> PV ----
        #pragma unroll
        for (int s = 0; s < 4; s++) {
            uint32_t pfh[2][4];   // fp16 A-fragments of P for this key group
            #pragma unroll
            for (int hhf = 0; hhf < 2; hhf++) {
                const int nt = 2 * s + hhf;
                float sf[2][4];
                #pragma unroll
                for (int mt = 0; mt < 2; mt++)
                    #pragma unroll
                    for (int e = 0; e < 4; e++) sf[mt][e] = 0.f;
                #pragma unroll
                for (int ks = 0; ks < 2; ks++) {
                    uint32_t aoff = bofs + (uint32_t)((nt * 8 + (lane & 7)) * ROWB
                                               + (ks * 16 + (lane >> 3) * 8) * 2);
                    uint32_t k0f, k1f;
                    LDMX2(k0f, k1f, sk0 + aoff);
                    #pragma unroll
                    for (int mt = 0; mt < 2; mt++)
                        mma_f16(sf[mt], qh[mt][ks], k0f, k1f);
                }
                #pragma unroll
                for (int mt = 0; mt < 2; mt++) {
                    float p0 = ex2f(sf[mt][0]);
                    float p1 = ex2f(sf[mt][1]);
                    float p2 = ex2f(sf[mt][2]);
                    float p3 = ex2f(sf[mt][3]);
                    lA[mt] += p0 + p1;
                    lB[mt] += p2 + p3;
                    pfh[mt][hhf * 2]     = pack_h2(p0, p1);
                    pfh[mt][hhf * 2 + 1] = pack_h2(p2, p3);
                }
            }
            // ---- O += P.v for keys [s*16, s*16+16) ----
            #pragma unroll
            for (int nt = 0; nt < 4; nt++) {
                uint32_t voff = bofs + (uint32_t)((s * 16 + lane) * ROWB + nt * 16);
                uint32_t v0f, v1f;
                LDMX2T(v0f, v1f, sv0 + voff);
                #pragma unroll
                for (int mt = 0; mt < 2; mt++)
                    mma_f16(of[mt][nt], pfh[mt], v0f, v1f);
            }
        }
        __syncthreads();
    }

    // ---- normalize + write g_aoh/g_aol [m][c] (bf16 hi/lo for proj) ----
    const int bb = bh / NHEAD, hh = bh % NHEAD;
    #pragma unroll
    for (int mt = 0; mt < 2; mt++) {
        float a = lA[mt], b2 = lB[mt];
        a  += __shfl_xor_sync(0xffffffffu, a, 1);
        a  += __shfl_xor_sync(0xffffffffu, a, 2);
        b2 += __shfl_xor_sync(0xffffffffu, b2, 1);
        b2 += __shfl_xor_sync(0xffffffffu, b2, 2);
        const float ia = 1.f / a, ib = 1.f / b2;
        const int rA = n0 + w * 32 + mt * 16 + g;
        const size_t baseA = ((size_t)(bb * NN) + rA) * CDIM + hh * DHEAD;
        const size_t baseB = baseA + (size_t)8 * CDIM;
        #pragma unroll
        for (int nt = 0; nt < 4; nt++) {
            int col = nt * 8 + t4 * 2;
            uint32_t h0, l0, h1, l1;
            split2(of[mt][nt][0] * ia, of[mt][nt][1] * ia, h0, l0);
            split2(of[mt][nt][2] * ib, of[mt][nt][3] * ib, h1, l1);
            *(uint32_t*)(g_aoh + baseA + col) = h0;
            *(uint32_t*)(g_aol + baseA + col) = l0;
            *(uint32_t*)(g_aoh + baseB + col) = h1;
            *(uint32_t*)(g_aol + baseB + col) = l1;
        }
    }
}

// ---------------------------------------------------------------------------
// Kernel 3: projection GEMM on mma.sync bf16x3 + bias (static k32, verified).
// ---------------------------------------------------------------------------
__global__ __launch_bounds__(256) void proj_mma(const float* __restrict__ bias,
                                                float* __restrict__ out) {
    __shared__ __align__(16) char sAh[128 * GROWB], sAl[128 * GROWB];
    __shared__ __align__(16) char sBh[128 * GROWB], sBl[128 * GROWB];

    const int tid  = threadIdx.x;
    const int w    = tid >> 5, lane = tid & 31;
    const int mw   = w & 1,   ow   = w >> 1;
    const int m0   = blockIdx.x * 128;
    const int o0   = blockIdx.y * 128;
    const int b    = m0 >> 10;

    const uint32_t ah_s = smem_u32(sAh), al_s = smem_u32(sAl);
    const uint32_t bh_s = smem_u32(sBh), bl_s = smem_u32(sBl);

    float acc[4][4][4];
    #pragma unroll
    for (int mt = 0; mt < 4; mt++)
        #pragma unroll
        for (int nt = 0; nt < 4; nt++)
            #pragma unroll
            for (int e = 0; e < 4; e++) acc[mt][nt][e] = 0.f;

    for (int it = 0; it < CDIM / 32; it++) {
        const int k0 = it * 32;
        __syncthreads();
        #pragma unroll
        for (int r = 0; r < 2; r++) {
            int idx = tid + 256 * r;
            int row = idx >> 2, c4 = idx & 3;
            size_t ga = (size_t)(m0 + row) * CDIM + k0 + c4 * 8;
            size_t gb = (size_t)(o0 + row) * CDIM + k0 + c4 * 8;
            *(uint4*)(sAh + row * GROWB + c4 * 16) = *(const uint4*)(g_aoh + ga);
            *(uint4*)(sAl + row * GROWB + c4 * 16) = *(const uint4*)(g_aol + ga);
            *(uint4*)(sBh + row * GROWB + c4 * 16) = *(const uint4*)(g_pwh + gb);
            *(uint4*)(sBl + row * GROWB + c4 * 16) = *(const uint4*)(g_pwl + gb);
        }
        __syncthreads();

        #pragma unroll
        for (int ks = 0; ks < 2; ks++) {
            uint32_t ah[4][4], al[4][4];
            const uint32_t aoff = (uint32_t)((mw * 64 + (lane & 15)) * GROWB
                                             + (ks * 16 + (lane >> 4) * 8) * 2);
            #pragma unroll
            for (int mt = 0; mt < 4; mt++) {
                LDMX4(ah[mt], ah_s + aoff + mt * 16 * GROWB);
                LDMX4(al[mt], al_s + aoff + mt * 16 * GROWB);
            }
            const uint32_t boff = (uint32_t)((ow * 32 + (lane & 7)) * GROWB
                                             + (ks * 16 + ((lane >> 3) & 1) * 8) * 2);
            #pragma unroll
            for (int nt = 0; nt < 4; nt++) {
                uint32_t b0, b1, c0r, c1;
                LDMX2(b0, b1, bh_s + boff + nt * 8 * GROWB);
                LDMX2(c0r, c1, bl_s + boff + nt * 8 * GROWB);
                #pragma unroll
                for (int mt = 0; mt < 4; mt++) {
                    mma_bf16(acc[mt][nt], ah[mt], b0, b1);
                    mma_bf16(acc[mt][nt], ah[mt], c0r, c1);
                    mma_bf16(acc[mt][nt], al[mt], b0, b1);
                }
            }
        }
    }

    // Epilogue: out[b][o][n] = acc + bias[o]
    const int g = lane >> 2, t4 = lane & 3;
    #pragma unroll
    for (int nt = 0; nt < 4; nt++) {
        const int o = o0 + ow * 32 + nt * 8 + t4 * 2;
        const float b0v = bias[o], b1v = bias[o + 1];
        float* r0 = out + ((size_t)b * CDIM + o) * NN;
        float* r1 = r0 + NN;
        #pragma unroll
        for (int mt = 0; mt < 4; mt++) {
            const int n = (m0 + mw * 64 + mt * 16 + g) & (NN - 1);
            float* ac = acc[mt][nt];
            r0[n]     = ac[0] + b0v;
            r1[n]     = ac[1] + b1v;
            r0[n + 8] = ac[2] + b0v;
            r1[n + 8] = ac[3] + b1v;
        }
    }
}

// ---------------------------------------------------------------------------
extern "C" void kernel_launch(void* const* d_in, const int* in_sizes, int n_in,
                              void* d_out, int out_size) {
    const float* x      = (const float*)d_in[0];   // [16,384,32,32]
    const float* qkv_w  = (const float*)d_in[1];   // [1152,384]
    const float* proj_w = (const float*)d_in[2];   // [384,384]
    const float* proj_b = (const float*)d_in[3];   // [384]
    float* out = (float*)d_out;                    // [16,384,32,32]

    convert_x<<<dim3(NN / 32, CDIM / 32, NB), dim3(32, 8)>>>(x);
    convert_w<<<(3 * CDIM * CDIM + 255) / 256, 256>>>(qkv_w, proj_w);
    qkv_mma<<<dim3(MT / 128, (3 * CDIM) / 128), 256>>>();
    attn_mma<<<dim3(NN / 128, NB * NHEAD), 128>>>();
    proj_mma<<<dim3(MT / 128, CDIM / 128), 256>>>(proj_b, out);
}

// round 15
// speedup vs baseline: 1.6329x; 1.0959x over previous
#include <cuda_runtime.h>
#include <cuda_bf16.h>
#include <cuda_fp16.h>
#include <cstdint>

// Problem constants
constexpr int CDIM  = 384;
constexpr int NHEAD = 12;
constexpr int DHEAD = 32;
constexpr int NB    = 16;
constexpr int NN    = 1024;            // 32*32 tokens
constexpr int MT    = NB * NN;         // 16384 rows
constexpr float QK_SCALE = 0.17677669529663687f; // 32^-0.5
constexpr float LOG2E    = 1.4426950408889634f;
constexpr float QS2      = QK_SCALE * LOG2E;     // folded into K at qkv epilogue

// Scratch (static device globals; no runtime allocation)
__device__ float  g_q [(size_t)NB * NHEAD * NN * DHEAD];  // fp32 Q
__device__ __half g_k [(size_t)NB * NHEAD * NN * DHEAD];  // fp16 K (pre-scaled)
__device__ __half g_v [(size_t)NB * NHEAD * NN * DHEAD];  // fp16 V
__device__ __half g_x [(size_t)MT * CDIM];        // x transposed [m][k], fp16
__device__ __half g_wh[(size_t)3 * CDIM * CDIM];  // qkv_w [o][k] fp16 hi
__device__ __half g_wl[(size_t)3 * CDIM * CDIM];  // qkv_w fp16 lo
__device__ __half g_pwh[(size_t)CDIM * CDIM];     // proj_w fp16 hi
__device__ __half g_pwl[(size_t)CDIM * CDIM];     // proj_w fp16 lo
__device__ __half g_ao[(size_t)MT * CDIM];        // attention out [m][c], fp16

// ===========================================================================
// Helpers
// ===========================================================================
__device__ __forceinline__ float ex2f(float x) {
    float y; asm("ex2.approx.ftz.f32 %0, %1;" : "=f"(y) : "f"(x)); return y;
}
// fp16 hi/lo split
__device__ __forceinline__ void split1h(float a, __half& h, __half& l) {
    h = __float2half_rn(a);
    l = __float2half_rn(a - __half2float(h));
}
__device__ __forceinline__ uint32_t pack_h2(float a, float b) {
    __half2 h = __floats2half2_rn(a, b);
    return *(uint32_t*)&h;
}
__device__ __forceinline__ uint32_t smem_u32(const void* p) {
    uint32_t a;
    asm("{ .reg .u64 t; cvta.to.shared.u64 t, %1; cvt.u32.u64 %0, t; }"
        : "=r"(a) : "l"(p));
    return a;
}
#define LDMX2(r0, r1, addr) \
    asm volatile("ldmatrix.sync.aligned.m8n8.x2.shared.b16 {%0,%1}, [%2];" \
                 : "=r"(r0), "=r"(r1) : "r"(addr))
#define LDMX2T(r0, r1, addr) \
    asm volatile("ldmatrix.sync.aligned.m8n8.x2.trans.shared.b16 {%0,%1}, [%2];" \
                 : "=r"(r0), "=r"(r1) : "r"(addr))
#define LDMX4(r, addr) \
    asm volatile("ldmatrix.sync.aligned.m8n8.x4.shared.b16 {%0,%1,%2,%3}, [%4];" \
                 : "=r"((r)[0]), "=r"((r)[1]), "=r"((r)[2]), "=r"((r)[3]) : "r"(addr))
__device__ __forceinline__ void mma_f16(float* d, const uint32_t* a,
                                        uint32_t b0, uint32_t b1) {
    asm volatile(
        "mma.sync.aligned.m16n8k16.row.col.f32.f16.f16.f32 "
        "{%0,%1,%2,%3}, {%4,%5,%6,%7}, {%8,%9}, {%0,%1,%2,%3};"
        : "+f"(d[0]), "+f"(d[1]), "+f"(d[2]), "+f"(d[3])
        : "r"(a[0]), "r"(a[1]), "r"(a[2]), "r"(a[3]), "r"(b0), "r"(b1));
}
#define CP_ASYNC16(saddr, gptr) \
    asm volatile("cp.async.ca.shared.global [%0], [%1], 16;" \
                 :: "r"(saddr), "l"(gptr) : "memory")
#define CP_COMMIT() asm volatile("cp.async.commit_group;" ::: "memory")
#define CP_WAIT(n)  asm volatile("cp.async.wait_group %0;" :: "n"(n) : "memory")

// ---------------------------------------------------------------------------
// Kernel 0a: transpose x [b,c,n] fp32 -> g_x [m=b*NN+n][k=c] fp16 single
// ---------------------------------------------------------------------------
__global__ __launch_bounds__(256) void convert_x(const float* __restrict__ x) {
    __shared__ float tile[32][33];
    const int b  = blockIdx.z;
    const int n0 = blockIdx.x * 32;
    const int c0 = blockIdx.y * 32;
    const int tx = threadIdx.x, ty = threadIdx.y;   // (32, 8)
    #pragma unroll
    for (int j = 0; j < 4; j++) {
        int c = c0 + ty + j * 8;
        tile[ty + j * 8][tx] = x[((size_t)b * CDIM + c) * NN + n0 + tx];
    }
    __syncthreads();
    #pragma unroll
    for (int j = 0; j < 4; j++) {
        int n = n0 + ty + j * 8;
        size_t idx = ((size_t)b * NN + n) * CDIM + c0 + tx;
        g_x[idx] = __float2half_rn(tile[tx][ty + j * 8]);
    }
}

// ---------------------------------------------------------------------------
// Kernel 0b: split weights (qkv_w and proj_w) into fp16 hi/lo.
// ---------------------------------------------------------------------------
__global__ __launch_bounds__(256) void convert_w(const float* __restrict__ qkv_w,
                                                 const float* __restrict__ proj_w) {
    const int i = blockIdx.x * 256 + threadIdx.x;
    const int NW = 3 * CDIM * CDIM;
    if (i < NW) {
        __half h, l; split1h(qkv_w[i], h, l);
        g_wh[i] = h; g_wl[i] = l;
    }
    if (i < CDIM * CDIM) {
        __half h, l; split1h(proj_w[i], h, l);
        g_pwh[i] = h; g_pwl[i] = l;
    }
}

// ---------------------------------------------------------------------------
// Kernel 1: QKV GEMM, fp16 2-term mma.sync: C = x_f16 . (wh + wl).
// Static k32 mainloop (structure verified). Block 128m x 128o, 8 warps.
// Epilogue: Q fp32; K fp16 single scaled by QS2; V fp16 single.
// ---------------------------------------------------------------------------
constexpr int GROWB = 80;   // 32 elems * 2B = 64B data + 16B pad

__global__ __launch_bounds__(256) void qkv_mma() {
    __shared__ __align__(16) char sA [128 * GROWB];
    __shared__ __align__(16) char sBh[128 * GROWB], sBl[128 * GROWB];

    const int tid  = threadIdx.x;
    const int w    = tid >> 5, lane = tid & 31;
    const int mw   = w & 1,   ow   = w >> 1;      // warp tile: 64m x 32o
    const int m0   = blockIdx.x * 128;
    const int o0   = blockIdx.y * 128;
    const int b    = m0 >> 10;

    const uint32_t a_s  = smem_u32(sA);
    const uint32_t bh_s = smem_u32(sBh), bl_s = smem_u32(sBl);

    float acc[4][4][4];
    #pragma unroll
    for (int mt = 0; mt < 4; mt++)
        #pragma unroll
        for (int nt = 0; nt < 4; nt++)
            #pragma unroll
            for (int e = 0; e < 4; e++) acc[mt][nt][e] = 0.f;

    for (int it = 0; it < CDIM / 32; it++) {
        const int k0 = it * 32;
        __syncthreads();
        #pragma unroll
        for (int r = 0; r < 2; r++) {
            int idx = tid + 256 * r;
            int row = idx >> 2, c4 = idx & 3;
            size_t ga = (size_t)(m0 + row) * CDIM + k0 + c4 * 8;
            size_t gb = (size_t)(o0 + row) * CDIM + k0 + c4 * 8;
            *(uint4*)(sA  + row * GROWB + c4 * 16) = *(const uint4*)(g_x  + ga);
            *(uint4*)(sBh + row * GROWB + c4 * 16) = *(const uint4*)(g_wh + gb);
            *(uint4*)(sBl + row * GROWB + c4 * 16) = *(const uint4*)(g_wl + gb);
        }
        __syncthreads();

        #pragma unroll
        for (int ks = 0; ks < 2; ks++) {
            uint32_t ah[4][4];
            const uint32_t aoff = (uint32_t)((mw * 64 + (lane & 15)) * GROWB
                                             + (ks * 16 + (lane >> 4) * 8) * 2);
            #pragma unroll
            for (int mt = 0; mt < 4; mt++)
                LDMX4(ah[mt], a_s + aoff + mt * 16 * GROWB);
            const uint32_t boff = (uint32_t)((ow * 32 + (lane & 7)) * GROWB
                                             + (ks * 16 + ((lane >> 3) & 1) * 8) * 2);
            #pragma unroll
            for (int nt = 0; nt < 4; nt++) {
                uint32_t b0, b1, c0r, c1;
                LDMX2(b0, b1, bh_s + boff + nt * 8 * GROWB);
                LDMX2(c0r, c1, bl_s + boff + nt * 8 * GROWB);
                #pragma unroll
                for (int mt = 0; mt < 4; mt++) {
                    mma_f16(acc[mt][nt], ah[mt], b0, b1);
                    mma_f16(acc[mt][nt], ah[mt], c0r, c1);
                }
            }
        }
    }

    // Epilogue: Q -> fp32; K -> fp16 (scaled by QS2); V -> fp16 single.
    const int g = lane >> 2, t4 = lane & 3;
    #pragma unroll
    for (int mt = 0; mt < 4; mt++) {
        const int n = (m0 + mw * 64 + mt * 16 + g) & (NN - 1);
        #pragma unroll
        for (int nt = 0; nt < 4; nt++) {
            const int o   = o0 + ow * 32 + nt * 8 + t4 * 2;
            const int wch = o / CDIM;
            const int rem = o % CDIM;
            const int h   = rem >> 5, d = rem & 31;
            const size_t base0 = ((size_t)(b * NHEAD + h) * NN + n) * DHEAD + d;
            const size_t base1 = base0 + 8 * DHEAD;   // row n+8
            float* ac = acc[mt][nt];
            if (wch == 0) {
                *(float2*)(g_q + base0) = make_float2(ac[0], ac[1]);
                *(float2*)(g_q + base1) = make_float2(ac[2], ac[3]);
            } else if (wch == 1) {
                *(uint32_t*)(g_k + base0) = pack_h2(ac[0] * QS2, ac[1] * QS2);
                *(uint32_t*)(g_k + base1) = pack_h2(ac[2] * QS2, ac[3] * QS2);
            } else {
                *(uint32_t*)(g_v + base0) = pack_h2(ac[0], ac[1]);
                *(uint32_t*)(g_v + base1) = pack_h2(ac[2], ac[3]);
            }
        }
    }
}

// ---------------------------------------------------------------------------
// Kernel 2: flash attention, fp16 mma.sync single-term (verified R14):
//   S = q_fp16 . k_fp16; P = fp16(exp2(S)); O += P . v_fp16
// Epilogue now writes g_ao as single fp16.
// ---------------------------------------------------------------------------
constexpr int ROWB = 80;

__global__ __launch_bounds__(128, 4) void attn_mma() {
    __shared__ __align__(16) char sk[2][64 * ROWB];
    __shared__ __align__(16) char sv[2][64 * ROWB];

    const int tid = threadIdx.x;
    const int w   = tid >> 5;
    const int l   = tid & 31;
    const int g   = l >> 2;
    const int t4  = l & 3;
    const int lane = l & 15;
    const int bh  = blockIdx.y;
    const int n0  = blockIdx.x * 128;

    const uint32_t sk0 = smem_u32(sk[0]);
    const uint32_t sv0 = smem_u32(sv[0]);
    constexpr uint32_t BUFB = 64 * ROWB;

    // ---- per-thread chunk-load geometry ----
    const int    ldrow = tid >> 2, ldc4 = tid & 3;
    const size_t ldsrc0 = ((size_t)bh * NN + ldrow) * DHEAD + ldc4 * 8;
    const uint32_t lddst = (uint32_t)(ldrow * ROWB + ldc4 * 16);
    const size_t ldsrc1 = ldsrc0 + (size_t)32 * DHEAD;
    const uint32_t lddst1 = lddst + 32 * ROWB;

    // ---- prologue: async-load chunk 0 into buffer 0 ----
    CP_ASYNC16(sk0 + lddst,  g_k + ldsrc0);
    CP_ASYNC16(sk0 + lddst1, g_k + ldsrc1);
    CP_ASYNC16(sv0 + lddst,  g_v + ldsrc0);
    CP_ASYNC16(sv0 + lddst1, g_v + ldsrc1);
    CP_COMMIT();

    // ---- Q fragments: single fp16 (no scale; folded into K) ----
    uint32_t qh[2][2][4];
    {
        const float* qb = g_q + ((size_t)bh * NN + n0 + w * 32) * DHEAD;
        #pragma unroll
        for (int mt = 0; mt < 2; mt++)
            #pragma unroll
            for (int ks = 0; ks < 2; ks++) {
                int rA = mt * 16 + g, rB = rA + 8, kk = ks * 16 + t4 * 2;
                float2 v0 = *(const float2*)(qb + rA * DHEAD + kk);
                float2 v1 = *(const float2*)(qb + rB * DHEAD + kk);
                float2 v2 = *(const float2*)(qb + rA * DHEAD + kk + 8);
                float2 v3 = *(const float2*)(qb + rB * DHEAD + kk + 8);
                qh[mt][ks][0] = pack_h2(v0.x, v0.y);
                qh[mt][ks][1] = pack_h2(v1.x, v1.y);
                qh[mt][ks][2] = pack_h2(v2.x, v2.y);
                qh[mt][ks][3] = pack_h2(v3.x, v3.y);
            }
    }

    float of[2][4][4];
    #pragma unroll
    for (int mt = 0; mt < 2; mt++)
        #pragma unroll
        for (int nt = 0; nt < 4; nt++)
            #pragma unroll
            for (int e = 0; e < 4; e++) of[mt][nt][e] = 0.f;

    float lA[2] = {0.f, 0.f}, lB[2] = {0.f, 0.f};

    for (int it = 0; it < 16; it++) {
        const uint32_t bofs = (uint32_t)(it & 1) * BUFB;
        if (it < 15) {
            const uint32_t nofs = (uint32_t)((it + 1) & 1) * BUFB;
            const size_t koff = (size_t)(it + 1) * 64 * DHEAD;
            CP_ASYNC16(sk0 + nofs + lddst,  g_k + ldsrc0 + koff);
            CP_ASYNC16(sk0 + nofs + lddst1, g_k + ldsrc1 + koff);
            CP_ASYNC16(sv0 + nofs + lddst,  g_v + ldsrc0 + koff);
            CP_ASYNC16(sv0 + nofs + lddst1, g_v + ldsrc1 + koff);
            CP_COMMIT();
            CP_WAIT(1);
        } else {
            CP_WAIT(0);
        }
        __syncthreads();

        // ---- interleaved: per 16-key group: S-mma -> exp -> pack -> PV ----
        #pragma unroll
        for (int s = 0; s < 4; s++) {
            uint32_t pfh[2][4];
            #pragma unroll
            for (int hhf = 0; hhf < 2; hhf++) {
                const int nt = 2 * s + hhf;
                float sf[2][4];
                #pragma unroll
                for (int mt = 0; mt < 2; mt++)
                    #pragma unroll
                    for (int e = 0; e < 4; e++) sf[mt][e] = 0.f;
                #pragma unroll
                for (int ks = 0; ks < 2; ks++) {
                    uint32_t aoff = bofs + (uint32_t)((nt * 8 + (lane & 7)) * ROWB
                                               + (ks * 16 + (lane >> 3) * 8) * 2);
                    uint32_t k0f, k1f;
                    LDMX2(k0f, k1f, sk0 + aoff);
                    #pragma unroll
                    for (int mt = 0; mt < 2; mt++)
                        mma_f16(sf[mt], qh[mt][ks], k0f, k1f);
                }
                #pragma unroll
                for (int mt = 0; mt < 2; mt++) {
                    float p0 = ex2f(sf[mt][0]);
                    float p1 = ex2f(sf[mt][1]);
                    float p2 = ex2f(sf[mt][2]);
                    float p3 = ex2f(sf[mt][3]);
                    lA[mt] += p0 + p1;
                    lB[mt] += p2 + p3;
                    pfh[mt][hhf * 2]     = pack_h2(p0, p1);
                    pfh[mt][hhf * 2 + 1] = pack_h2(p2, p3);
                }
            }
            // ---- O += P.v for keys [s*16, s*16+16) ----
            #pragma unroll
            for (int nt = 0; nt < 4; nt++) {
                uint32_t voff = bofs + (uint32_t)((s * 16 + lane) * ROWB + nt * 16);
                uint32_t v0f, v1f;
                LDMX2T(v0f, v1f, sv0 + voff);
                #pragma unroll
                for (int mt = 0; mt < 2; mt++)
                    mma_f16(of[mt][nt], pfh[mt], v0f, v1f);
            }
        }
        __syncthreads();
    }

    // ---- normalize + write g_ao [m][c] fp16 single (proj A-side) ----
    const int bb = bh / NHEAD, hh = bh % NHEAD;
    #pragma unroll
    for (int mt = 0; mt < 2; mt++) {
        float a = lA[mt], b2 = lB[mt];
        a  += __shfl_xor_sync(0xffffffffu, a, 1);
        a  += __shfl_xor_sync(0xffffffffu, a, 2);
        b2 += __shfl_xor_sync(0xffffffffu, b2, 1);
        b2 += __shfl_xor_sync(0xffffffffu, b2, 2);
        const float ia = 1.f / a, ib = 1.f / b2;
        const int rA = n0 + w * 32 + mt * 16 + g;
        const size_t baseA = ((size_t)(bb * NN) + rA) * CDIM + hh * DHEAD;
        const size_t baseB = baseA + (size_t)8 * CDIM;
        #pragma unroll
        for (int nt = 0; nt < 4; nt++) {
            int col = nt * 8 + t4 * 2;
            *(uint32_t*)(g_ao + baseA + col) =
                pack_h2(of[mt][nt][0] * ia, of[mt][nt][1] * ia);
            *(uint32_t*)(g_ao + baseB + col) =
                pack_h2(of[mt][nt][2] * ib, of[mt][nt][3] * ib);
        }
    }
}

// ---------------------------------------------------------------------------
// Kernel 3: projection GEMM, fp16 2-term: out = ao_f16 . (pwh + pwl) + bias.
// ---------------------------------------------------------------------------
__global__ __launch_bounds__(256) void proj_mma(const float* __restrict__ bias,
                                                float* __restrict__ out) {
    __shared__ __align__(16) char sA [128 * GROWB];
    __shared__ __align__(16) char sBh[128 * GROWB], sBl[128 * GROWB];

    const int tid  = threadIdx.x;
    const int w    = tid >> 5, lane = tid & 31;
    const int mw   = w & 1,   ow   = w >> 1;
    const int m0   = blockIdx.x * 128;
    const int o0   = blockIdx.y * 128;
    const int b    = m0 >> 10;

    const uint32_t a_s  = smem_u32(sA);
    const uint32_t bh_s = smem_u32(sBh), bl_s = smem_u32(sBl);

    float acc[4][4][4];
    #pragma unroll
    for (int mt = 0; mt < 4; mt++)
        #pragma unroll
        for (int nt = 0; nt < 4; nt++)
            #pragma unroll
            for (int e = 0; e < 4; e++) acc[mt][nt][e] = 0.f;

    for (int it = 0; it < CDIM / 32; it++) {
        const int k0 = it * 32;
        __syncthreads();
        #pragma unroll
        for (int r = 0; r < 2; r++) {
            int idx = tid + 256 * r;
            int row = idx >> 2, c4 = idx & 3;
            size_t ga = (size_t)(m0 + row) * CDIM + k0 + c4 * 8;
            size_t gb = (size_t)(o0 + row) * CDIM + k0 + c4 * 8;
            *(uint4*)(sA  + row * GROWB + c4 * 16) = *(const uint4*)(g_ao  + ga);
            *(uint4*)(sBh + row * GROWB + c4 * 16) = *(const uint4*)(g_pwh + gb);
            *(uint4*)(sBl + row * GROWB + c4 * 16) = *(const uint4*)(g_pwl + gb);
        }
        __syncthreads();

        #pragma unroll
        for (int ks = 0; ks < 2; ks++) {
            uint32_t ah[4][4];
            const uint32_t aoff = (uint32_t)((mw * 64 + (lane & 15)) * GROWB
                                             + (ks * 16 + (lane >> 4) * 8) * 2);
            #pragma unroll
            for (int mt = 0; mt < 4; mt++)
                LDMX4(ah[mt], a_s + aoff + mt * 16 * GROWB);
            const uint32_t boff = (uint32_t)((ow * 32 + (lane & 7)) * GROWB
                                             + (ks * 16 + ((lane >> 3) & 1) * 8) * 2);
            #pragma unroll
            for (int nt = 0; nt < 4; nt++) {
                uint32_t b0, b1, c0r, c1;
                LDMX2(b0, b1, bh_s + boff + nt * 8 * GROWB);
                LDMX2(c0r, c1, bl_s + boff + nt * 8 * GROWB);
                #pragma unroll
                for (int mt = 0; mt < 4; mt++) {
                    mma_f16(acc[mt][nt], ah[mt], b0, b1);
                    mma_f16(acc[mt][nt], ah[mt], c0r, c1);
                }
            }
        }
    }

    // Epilogue: out[b][o][n] = acc + bias[o]
    const int g = lane >> 2, t4 = lane & 3;
    #pragma unroll
    for (int nt = 0; nt < 4; nt++) {
        const int o = o0 + ow * 32 + nt * 8 + t4 * 2;
        const float b0v = bias[o], b1v = bias[o + 1];
        float* r0 = out + ((size_t)b * CDIM + o) * NN;
        float* r1 = r0 + NN;
        #pragma unroll
        for (int mt = 0; mt < 4; mt++) {
            const int n = (m0 + mw * 64 + mt * 16 + g) & (NN - 1);
            float* ac = acc[mt][nt];
            r0[n]     = ac[0] + b0v;
            r1[n]     = ac[1] + b1v;
            r0[n + 8] = ac[2] + b0v;
            r1[n + 8] = ac[3] + b1v;
        }
    }
}

// ---------------------------------------------------------------------------
extern "C" void kernel_launch(void* const* d_in, const int* in_sizes, int n_in,
                              void* d_out, int out_size) {
    const float* x      = (const float*)d_in[0];   // [16,384,32,32]
    const float* qkv_w  = (const float*)d_in[1];   // [1152,384]
    const float* proj_w = (const float*)d_in[2];   // [384,384]
    const float* proj_b = (const float*)d_in[3];   // [384]
    float* out = (float*)d_out;                    // [16,384,32,32]

    convert_x<<<dim3(NN / 32, CDIM / 32, NB), dim3(32, 8)>>>(x);
    convert_w<<<(3 * CDIM * CDIM + 255) / 256, 256>>>(qkv_w, proj_w);
    qkv_mma<<<dim3(MT / 128, (3 * CDIM) / 128), 256>>>();
    attn_mma<<<dim3(NN / 128, NB * NHEAD), 128>>>();
    proj_mma<<<dim3(MT / 128, CDIM / 128), 256>>>(proj_b, out);
}